// round 14
// baseline (speedup 1.0000x reference)
#include <cuda_runtime.h>
#include <cuda_fp16.h>
#include <math.h>
#include <stdint.h>

#define N_NODE 10000
#define N_EDGE 320000
#define HID    128
#define NC     4

// ------- edge kernel: persistent, 64 edges/tile, 512 thr, occ 1 ------------
#define ME      64
#define ETHREADS 512
#define NT      (N_EDGE / ME)     // 5000 tiles
#define EGRID   148
#define LDA_B   656               // A row stride bytes
#define LDB_B   272               // B row stride bytes (136 fp16)
#define A_OFF   0                 // 64*656 = 41984
#define W_OFF   41984             // 544 rows x 272 = 147968 (W1:0, W2:288, W3:416)
#define W1ROW   0
#define W2ROW   288
#define W3ROW   416
#define OF_ROW  189952
#define OF_COL  190208
#define OF_INV  190464
#define OF_B1   190592
#define OF_B2   191104
#define OF_B3   191616
#define OF_CW   192128            // transposed c_wout: 4 x 136 fp32 = 2176
#define OF_CD   194304            // coord_diff: 64*12*4 = 3072
#define SMEM_EDGE_BYTES 197376

// ------- node kernel geometry (64 rows/CTA, 256 thr, occ 3) ----------------
#define NTHREADS 256
#define MN      64
#define NA_OFF  0
#define NB_OFF  41984
#define NOF_BIAS 59392
#define SMEM_NODE_BYTES 60544

// ---------------- scratch ----------------
__device__ float g_sumsq[32];
__device__ float g_nagg[N_NODE * HID];
__device__ float g_agg[N_NODE * NC * 3];
__device__ float g_cnt[N_NODE];
// weight images: [K x 128] fp16, row stride 272 B
__device__ __align__(16) unsigned char g_w1t[288 * LDB_B];
__device__ __align__(16) unsigned char g_w2t[128 * LDB_B];
__device__ __align__(16) unsigned char g_w3t[128 * LDB_B];
__device__ __align__(16) unsigned char g_nw1t[256 * LDB_B];
__device__ __align__(16) unsigned char g_nw2t[128 * LDB_B];

__device__ __forceinline__ float silu_f(float x) {
    return __fdividef(x, 1.0f + __expf(-x));
}
__device__ __forceinline__ uint32_t smem_to_u32(const void* p) {
    uint32_t a;
    asm("{ .reg .u64 t; cvta.to.shared.u64 t, %1; cvt.u32.u64 %0, t; }" : "=r"(a) : "l"(p));
    return a;
}
__device__ __forceinline__ void ldm_x4(uint32_t (&r)[4], uint32_t addr) {
    asm volatile("ldmatrix.sync.aligned.m8n8.x4.shared.b16 {%0,%1,%2,%3}, [%4];"
                 : "=r"(r[0]), "=r"(r[1]), "=r"(r[2]), "=r"(r[3]) : "r"(addr));
}
__device__ __forceinline__ void ldm_x4_t(uint32_t (&r)[4], uint32_t addr) {
    asm volatile("ldmatrix.sync.aligned.m8n8.x4.trans.shared.b16 {%0,%1,%2,%3}, [%4];"
                 : "=r"(r[0]), "=r"(r[1]), "=r"(r[2]), "=r"(r[3]) : "r"(addr));
}
__device__ __forceinline__ void mma_f16(float (&d)[4], const uint32_t (&a)[4],
                                        uint32_t b0, uint32_t b1) {
    asm volatile("mma.sync.aligned.m16n8k16.row.col.f32.f16.f16.f32 "
                 "{%0,%1,%2,%3}, {%4,%5,%6,%7}, {%8,%9}, {%0,%1,%2,%3};"
                 : "+f"(d[0]), "+f"(d[1]), "+f"(d[2]), "+f"(d[3])
                 : "r"(a[0]), "r"(a[1]), "r"(a[2]), "r"(a[3]), "r"(b0), "r"(b1));
}
__device__ __forceinline__ void cp_async16(uint32_t dst, const void* src) {
    asm volatile("cp.async.cg.shared.global [%0], [%1], 16;" :: "r"(dst), "l"(src));
}
#define CP_COMMIT() asm volatile("cp.async.commit_group;" ::: "memory")
#define CP_WAIT0()  asm volatile("cp.async.wait_group 0;" ::: "memory")

__device__ __forceinline__ uint32_t pack2h(float a, float b) {
    __half2 t = __floats2half2_rn(a, b);
    return *reinterpret_cast<uint32_t*>(&t);
}
__device__ __forceinline__ void store4A(unsigned char* sm, int e, int col, float4 v) {
    uint32_t off = (uint32_t)(e * LDA_B + col * 2);
    *(uint2*)(sm + off) = make_uint2(pack2h(v.x, v.y), pack2h(v.z, v.w));
}

// ============================================================================
// Fused prep (weights -> fp16 images) + sumsq (L2-norm sums over edges).
// ============================================================================
#define PREP_BLOCKS  464
#define SUMSQ_BLOCKS 1184

__global__ void prep_sumsq_kernel(const float* __restrict__ w1,
                                  const float* __restrict__ w2,
                                  const float* __restrict__ w3,
                                  const float* __restrict__ nw1,
                                  const float* __restrict__ nw2,
                                  const float* __restrict__ coord,
                                  const int* __restrict__ row,
                                  const int* __restrict__ col)
{
    int tid = threadIdx.x;
    if (blockIdx.x < PREP_BLOCKS) {
        int idx = blockIdx.x * 256 + tid;
        const float* W; unsigned char* dst; int r;
        if (idx < 36864)       { W = w1;  dst = g_w1t;  r = idx; }
        else if (idx < 53248)  { W = w2;  dst = g_w2t;  r = idx - 36864; }
        else if (idx < 69632)  { W = w3;  dst = g_w3t;  r = idx - 53248; }
        else if (idx < 102400) { W = nw1; dst = g_nw1t; r = idx - 69632; }
        else if (idx < 118784) { W = nw2; dst = g_nw2t; r = idx - 102400; }
        else return;
        int kk = r >> 7, n = r & 127;
        *(__half*)(dst + kk * LDB_B + n * 2) = __float2half_rn(W[kk * 128 + n]);
        return;
    }
    __shared__ float s_sum[32];
    if (tid < 32) s_sum[tid] = 0.0f;
    __syncthreads();
    float p[32];
#pragma unroll
    for (int i = 0; i < 32; i++) p[i] = 0.0f;
    int bid = blockIdx.x - PREP_BLOCKS;
    for (int e = bid * 256 + tid; e < N_EDGE; e += SUMSQ_BLOCKS * 256) {
        const float4* c4i = (const float4*)(coord + row[e] * 12);
        const float4* c4j = (const float4*)(coord + col[e] * 12);
        float4 i0 = c4i[0], i1 = c4i[1], i2 = c4i[2];
        float4 j0 = c4j[0], j1 = c4j[1], j2 = c4j[2];
        float a[12] = {i0.x,i0.y,i0.z,i0.w,i1.x,i1.y,i1.z,i1.w,i2.x,i2.y,i2.z,i2.w};
        float b[12] = {j0.x,j0.y,j0.z,j0.w,j1.x,j1.y,j1.z,j1.w,j2.x,j2.y,j2.z,j2.w};
        float d[12];
#pragma unroll
        for (int i = 0; i < 12; i++) d[i] = a[i] - b[i];
#pragma unroll
        for (int c = 0; c < 4; c++) {
#pragma unroll
            for (int f = 0; f < 4; f++) {
                float r = d[c*3+0]*d[f*3+0] + d[c*3+1]*d[f*3+1] + d[c*3+2]*d[f*3+2];
                float dx = a[c*3+0]-b[f*3+0], dy = a[c*3+1]-b[f*3+1], dz = a[c*3+2]-b[f*3+2];
                float d2 = dx*dx + dy*dy + dz*dz;
                p[c*8 + f]     += r * r;
                p[c*8 + 4 + f] += d2;
            }
        }
    }
#pragma unroll
    for (int i = 0; i < 32; i++) atomicAdd(&s_sum[i], p[i]);
    __syncthreads();
    if (tid < 32) atomicAdd(&g_sumsq[tid], s_sum[tid]);
}

// ============================================================================
// EDGE GEMM: 16 warps in 2x8 grid, warp tile 32 rows x 16 cols, acc[2][2][4].
// All weights resident in smem -> straight-line k-loop, no syncs, no staging.
// ============================================================================
template <int KTOT>
__device__ __forceinline__ void run_gemm_e(
    uint32_t smem_base, float (&acc)[2][2][4],
    int a_col_base, int wrow0, int lane, int r0, int n0)
{
#pragma unroll
    for (int mt = 0; mt < 2; mt++)
#pragma unroll
        for (int nb = 0; nb < 2; nb++)
#pragma unroll
            for (int i = 0; i < 4; i++) acc[mt][nb][i] = 0.0f;

    uint32_t a_base = smem_base + A_OFF +
        (uint32_t)((r0 + (lane & 15)) * LDA_B + (a_col_base + (lane >> 4) * 8) * 2);
    uint32_t b_base = smem_base + W_OFF +
        (uint32_t)((wrow0 + (lane & 15)) * LDB_B + (n0 + (lane >> 4) * 8) * 2);

#pragma unroll
    for (int ks = 0; ks < KTOT / 16; ks++) {
        uint32_t ah[2][4];
        ldm_x4(ah[0], a_base + ks * 32);
        ldm_x4(ah[1], a_base + ks * 32 + 16 * LDA_B);
        uint32_t bh[4];
        ldm_x4_t(bh, b_base + ks * 16 * LDB_B);
        mma_f16(acc[0][0], ah[0], bh[0], bh[1]);
        mma_f16(acc[0][1], ah[0], bh[2], bh[3]);
        mma_f16(acc[1][0], ah[1], bh[0], bh[1]);
        mma_f16(acc[1][1], ah[1], bh[2], bh[3]);
    }
}

// bias + silu + fp16-store to A cols [dstbase, dstbase+128)
__device__ __forceinline__ void epi_store_e(
    unsigned char* sm, float (&acc)[2][2][4], const float* __restrict__ SBIAS,
    int dstbase, int lane, int r0, int n0)
{
#pragma unroll
    for (int mt = 0; mt < 2; mt++) {
        int ra = r0 + mt * 16 + (lane >> 2);
        int rb = ra + 8;
#pragma unroll
        for (int nb = 0; nb < 2; nb++) {
            int c = n0 + nb * 8 + (lane & 3) * 2;
            float b0 = SBIAS[c], b1 = SBIAS[c + 1];
            float v0 = silu_f(acc[mt][nb][0] + b0);
            float v1 = silu_f(acc[mt][nb][1] + b1);
            float v2 = silu_f(acc[mt][nb][2] + b0);
            float v3 = silu_f(acc[mt][nb][3] + b1);
            *(uint32_t*)(sm + ra * LDA_B + (dstbase + c) * 2) = pack2h(v0, v1);
            *(uint32_t*)(sm + rb * LDA_B + (dstbase + c) * 2) = pack2h(v2, v3);
        }
    }
}

// ============================================================================
// Persistent fused edge kernel: grid 148, 512 threads, 1 CTA/SM, ~34 tiles ea.
// ============================================================================
__global__ void __launch_bounds__(ETHREADS, 1)
edge_kernel(const float* __restrict__ h, const float* __restrict__ coord,
            const int* __restrict__ row, const int* __restrict__ col,
            const float* __restrict__ e_b1, const float* __restrict__ e_b2,
            const float* __restrict__ c_b1, const float* __restrict__ c_wout)
{
    extern __shared__ unsigned char sm[];
    const int tid  = threadIdx.x;
    const int wid  = tid >> 5;
    const int lane = tid & 31;
    uint32_t smem_base = smem_to_u32(sm);

    int*   SROW = (int*)(sm + OF_ROW);
    int*   SCOL = (int*)(sm + OF_COL);
    float* SINV = (float*)(sm + OF_INV);
    float* SB1  = (float*)(sm + OF_B1);
    float* SB2  = (float*)(sm + OF_B2);
    float* SB3  = (float*)(sm + OF_B3);
    float* SCWT = (float*)(sm + OF_CW);
    float* SCD  = (float*)(sm + OF_CD);

    // ---- one-time: load all weight images into smem (cp.async) ----
    for (int idx = tid; idx < 9248; idx += ETHREADS) {
        const unsigned char* src;
        int off;
        if (idx < 4896)      { src = g_w1t; off = idx; }
        else if (idx < 7072) { src = g_w2t; off = idx - 4896; }
        else                 { src = g_w3t; off = idx - 7072; }
        cp_async16(smem_base + W_OFF + idx * 16, src + off * 16);
    }
    CP_COMMIT();
    // ---- one-time constants ----
    if (tid < 128) { SB1[tid] = e_b1[tid]; SB2[tid] = e_b2[tid]; SB3[tid] = c_b1[tid]; }
    if (tid < 32)  SINV[tid] = 1.0f / fmaxf(sqrtf(g_sumsq[tid]), 1e-12f);
    if (tid < 256) {   // transpose c_wout [128][4] -> SCWT [4][136]
        int k = tid >> 1, half = tid & 1;
        float2 v = ((const float2*)c_wout)[tid];
        SCWT[(half * 2 + 0) * 136 + k] = v.x;
        SCWT[(half * 2 + 1) * 136 + k] = v.y;
    }
    CP_WAIT0();
    __syncthreads();

    const int wm = wid & 1, wn = wid >> 1;
    const int r0 = wm * 32, n0 = wn * 16;
    float acc[2][2][4];

    for (int t = blockIdx.x; t < NT; t += EGRID) {
        const int e0 = t * ME;
        if (tid < ME) { SROW[tid] = row[e0 + tid]; SCOL[tid] = col[e0 + tid]; }
        __syncthreads();

        // ---- gather h[row]|h[col] into A cols 0..255 (fp16) ----
#pragma unroll 2
        for (int idx = tid; idx < ME * 64; idx += ETHREADS) {
            int e = idx >> 6, p4 = idx & 63;
            int half = p4 >> 5, q = p4 & 31;
            int node = half ? SCOL[e] : SROW[e];
            float4 v = ((const float4*)(h + node * HID))[q];
            store4A(sm, e, half * 128 + q * 4, v);
        }
        // ---- rad features cols 256..287; coord_diff to SCD ----
        if (tid < ME) {
            int e = tid;
            const float4* c4i = (const float4*)(coord + SROW[e] * 12);
            const float4* c4j = (const float4*)(coord + SCOL[e] * 12);
            float4 i0 = c4i[0], i1 = c4i[1], i2 = c4i[2];
            float4 j0 = c4j[0], j1 = c4j[1], j2 = c4j[2];
            float a[12] = {i0.x,i0.y,i0.z,i0.w,i1.x,i1.y,i1.z,i1.w,i2.x,i2.y,i2.z,i2.w};
            float b[12] = {j0.x,j0.y,j0.z,j0.w,j1.x,j1.y,j1.z,j1.w,j2.x,j2.y,j2.z,j2.w};
            float d[12];
#pragma unroll
            for (int i = 0; i < 12; i++) { d[i] = a[i] - b[i]; SCD[e * 12 + i] = d[i]; }
            float radv[32];
#pragma unroll
            for (int c = 0; c < 4; c++) {
#pragma unroll
                for (int f = 0; f < 4; f++) {
                    float r = d[c*3+0]*d[f*3+0] + d[c*3+1]*d[f*3+1] + d[c*3+2]*d[f*3+2];
                    float dx = a[c*3+0]-b[f*3+0], dy = a[c*3+1]-b[f*3+1], dz = a[c*3+2]-b[f*3+2];
                    float d2 = dx*dx + dy*dy + dz*dz;
                    radv[c*8 + f]     = r * SINV[c*8 + f];
                    radv[c*8 + 4 + f] = sqrtf(d2) * SINV[c*8 + 4 + f];
                }
            }
#pragma unroll
            for (int q = 0; q < 32; q += 4)
                store4A(sm, e, 256 + q,
                        make_float4(radv[q], radv[q+1], radv[q+2], radv[q+3]));
        }
        __syncthreads();

        // ===== GEMM1: t1 = silu(eh @ W1 + b1) -> A cols 0..127 (K=288) =====
        run_gemm_e<288>(smem_base, acc, 0, W1ROW, lane, r0, n0);
        __syncthreads();
        epi_store_e(sm, acc, SB1, 0, lane, r0, n0);
        __syncthreads();

        // ===== GEMM2: m = silu(t1 @ W2 + b2) -> A cols 128..255 ============
        run_gemm_e<128>(smem_base, acc, 0, W2ROW, lane, r0, n0);
        __syncthreads();
        epi_store_e(sm, acc, SB2, 128, lane, r0, n0);
        __syncthreads();

        // ---- nagg scatter: coalesced red.v4 from fp16 m in smem ----
#pragma unroll 2
        for (int idx = tid; idx < ME * 32; idx += ETHREADS) {
            int e = idx >> 5, q = (idx & 31) * 4;
            uint2 hv = *(const uint2*)(sm + e * LDA_B + (128 + q) * 2);
            __half2 p0 = *reinterpret_cast<__half2*>(&hv.x);
            __half2 p1 = *reinterpret_cast<__half2*>(&hv.y);
            float2 f0 = __half22float2(p0), f1 = __half22float2(p1);
            float* dst = g_nagg + (size_t)SROW[e] * HID + q;
            asm volatile("red.global.add.v4.f32 [%0], {%1,%2,%3,%4};"
                         :: "l"(dst), "f"(f0.x), "f"(f0.y), "f"(f1.x), "f"(f1.y)
                         : "memory");
        }

        // ===== GEMM3: t2 = silu(m @ c_w1 + b) -> fp32 buffer ===============
        run_gemm_e<128>(smem_base, acc, 128, W3ROW, lane, r0, n0);
        __syncthreads();
        {
            float* t2f = (float*)sm;     // [64 x 132] fp32 overlays A
#pragma unroll
            for (int mt = 0; mt < 2; mt++) {
                int ra = r0 + mt * 16 + (lane >> 2);
                int rb = ra + 8;
#pragma unroll
                for (int nb = 0; nb < 2; nb++) {
                    int c = n0 + nb * 8 + (lane & 3) * 2;
                    float b0 = SB3[c], b1 = SB3[c + 1];
                    *(float2*)(t2f + ra * 132 + c) =
                        make_float2(silu_f(acc[mt][nb][0] + b0),
                                    silu_f(acc[mt][nb][1] + b1));
                    *(float2*)(t2f + rb * 132 + c) =
                        make_float2(silu_f(acc[mt][nb][2] + b0),
                                    silu_f(acc[mt][nb][3] + b1));
                }
            }
        }
        __syncthreads();

        // ===== w = t2 @ c_wout (float4 dot); coord atomics =================
        if (tid < ME * 4) {
            int e = tid >> 2, c = tid & 3;
            const float4* tr4 = (const float4*)((const float*)sm + e * 132);
            const float4* cw4 = (const float4*)(SCWT + c * 136);
            float w = 0.0f;
#pragma unroll
            for (int i = 0; i < 32; i++) {
                float4 tv = tr4[i], uq = cw4[i];
                w += tv.x * uq.x + tv.y * uq.y + tv.z * uq.z + tv.w * uq.w;
            }
            int node = SROW[e];
            const float* cd = SCD + e * 12 + c * 3;
            atomicAdd(&g_agg[node * 12 + c * 3 + 0], cd[0] * w);
            atomicAdd(&g_agg[node * 12 + c * 3 + 1], cd[1] * w);
            atomicAdd(&g_agg[node * 12 + c * 3 + 2], cd[2] * w);
            if (c == 0) atomicAdd(&g_cnt[node], 1.0f);
        }
        __syncthreads();   // t2f/SCD/SROW consumers done before next tile
    }
}

// ============================================================================
// NODE GEMM machinery (64 rows/CTA, 256 threads, 2x4 warp grid, tile 32x32)
// ============================================================================
#define NSTG 5

__device__ __forceinline__ void ld_stageN(uint4 (&stg)[NSTG],
                                          const unsigned char* __restrict__ wsrc,
                                          int byteoff, int n4, int tid)
{
    const uint4* s = (const uint4*)(wsrc + byteoff);
#pragma unroll
    for (int i = 0; i < NSTG; i++) {
        int idx = tid + i * NTHREADS;
        if (idx < n4) stg[i] = s[idx];
    }
}

template <int KTOT>
__device__ __forceinline__ void run_gemm_n(
    unsigned char* sm, uint32_t smem_base, float (&acc)[2][4][4],
    int a_col_base, const unsigned char* __restrict__ wsrc,
    int tid, int lane, int r0, int n0)
{
#pragma unroll
    for (int mt = 0; mt < 2; mt++)
#pragma unroll
        for (int nb = 0; nb < 4; nb++)
#pragma unroll
            for (int i = 0; i < 4; i++) acc[mt][nb][i] = 0.0f;

    uint4 stg[NSTG];
    constexpr int R0 = (KTOT < 64) ? KTOT : 64;
    ld_stageN(stg, wsrc, 0, R0 * 17, tid);

#pragma unroll
    for (int k0 = 0; k0 < KTOT; k0 += 64) {
        const int rows = (KTOT - k0 < 64) ? (KTOT - k0) : 64;
        const int cn4 = rows * 17;
        __syncthreads();
        {
            uint4* db = (uint4*)(sm + NB_OFF);
#pragma unroll
            for (int i = 0; i < NSTG; i++) {
                int idx = tid + i * NTHREADS;
                if (idx < cn4) db[idx] = stg[i];
            }
        }
        __syncthreads();
        if (k0 + 64 < KTOT) {
            const int nrows = (KTOT - k0 - 64 < 64) ? (KTOT - k0 - 64) : 64;
            ld_stageN(stg, wsrc, (k0 + 64) * LDB_B, nrows * 17, tid);
        }
        const int nks = rows >> 4;
#pragma unroll
        for (int ks = 0; ks < 4; ks++) {
            if (ks >= nks) break;
            int kcol = a_col_base + k0 + ks * 16;
            uint32_t ah[2][4];
            uint32_t a_off = (uint32_t)((r0 + (lane & 15)) * LDA_B + (kcol + (lane >> 4) * 8) * 2);
            ldm_x4(ah[0], smem_base + NA_OFF + a_off);
            ldm_x4(ah[1], smem_base + NA_OFF + a_off + 16 * LDA_B);
            uint32_t bh[2][4];
            uint32_t b_off = (uint32_t)((ks * 16 + (lane & 15)) * LDB_B + (n0 + (lane >> 4) * 8) * 2);
#pragma unroll
            for (int nt = 0; nt < 2; nt++)
                ldm_x4_t(bh[nt], smem_base + NB_OFF + b_off + nt * 32);
#pragma unroll
            for (int mt = 0; mt < 2; mt++)
#pragma unroll
                for (int nt = 0; nt < 2; nt++) {
                    mma_f16(acc[mt][2*nt],   ah[mt], bh[nt][0], bh[nt][1]);
                    mma_f16(acc[mt][2*nt+1], ah[mt], bh[nt][2], bh[nt][3]);
                }
        }
    }
    __syncthreads();
}

__global__ void __launch_bounds__(NTHREADS, 3)
node_kernel(const float* __restrict__ h, const float* __restrict__ coord,
            const float* __restrict__ n_b1, const float* __restrict__ n_b2,
            float* __restrict__ out_h, float* __restrict__ out_coord)
{
    extern __shared__ unsigned char sm[];
    const int tid  = threadIdx.x;
    const int wid  = tid >> 5;
    const int lane = tid & 31;
    const int nb0  = blockIdx.x * MN;
    uint32_t smem_base = smem_to_u32(sm);
    float* SBIAS = (float*)(sm + NOF_BIAS);

    // ---- gather h[n] | nagg[n] into A cols 0..255 (fp16) ----
#pragma unroll 4
    for (int idx = tid; idx < MN * 64; idx += NTHREADS) {
        int r = idx >> 6, p4 = idx & 63;
        int half = p4 >> 5, q = p4 & 31;
        int n = nb0 + r;
        float4 v = make_float4(0.f, 0.f, 0.f, 0.f);
        if (n < N_NODE)
            v = half ? ((const float4*)(g_nagg + n * HID))[q]
                     : ((const float4*)(h + n * HID))[q];
        store4A(sm, r, half * 128 + q * 4, v);
    }

    const int wm = wid & 1, wn = wid >> 1;
    const int r0 = wm * 32, n0 = wn * 32;
    float acc[2][4][4];

    // ========== GEMM1: t = silu(nin @ nW1 + b1) -> A cols 0..127 ==========
    if (tid < 128) SBIAS[tid] = n_b1[tid];
    run_gemm_n<256>(sm, smem_base, acc, 0, g_nw1t, tid, lane, r0, n0);
    {
#pragma unroll
        for (int mt = 0; mt < 2; mt++) {
            int ra = r0 + mt * 16 + (lane >> 2);
            int rb = ra + 8;
#pragma unroll
            for (int nb = 0; nb < 4; nb++) {
                int c = n0 + nb * 8 + (lane & 3) * 2;
                float b0 = SBIAS[c], b1 = SBIAS[c + 1];
                *(uint32_t*)(sm + ra * LDA_B + c * 2) =
                    pack2h(silu_f(acc[mt][nb][0] + b0), silu_f(acc[mt][nb][1] + b1));
                *(uint32_t*)(sm + rb * LDA_B + c * 2) =
                    pack2h(silu_f(acc[mt][nb][2] + b0), silu_f(acc[mt][nb][3] + b1));
            }
        }
    }
    __syncthreads();

    // ========== GEMM2: hn = t @ nW2 + b2 ; out_h = h + hn =================
    if (tid < 128) SBIAS[tid] = n_b2[tid];
    run_gemm_n<128>(sm, smem_base, acc, 0, g_nw2t, tid, lane, r0, n0);
    {
#pragma unroll
        for (int mt = 0; mt < 2; mt++) {
            int ra = r0 + mt * 16 + (lane >> 2);
            int rb = ra + 8;
            int na = nb0 + ra, nbv = nb0 + rb;
#pragma unroll
            for (int nb = 0; nb < 4; nb++) {
                int c = n0 + nb * 8 + (lane & 3) * 2;
                float b0 = SBIAS[c], b1 = SBIAS[c + 1];
                if (na < N_NODE) {
                    float2 hv = *(const float2*)(h + na * HID + c);
                    *(float2*)(out_h + na * HID + c) =
                        make_float2(acc[mt][nb][0] + b0 + hv.x,
                                    acc[mt][nb][1] + b1 + hv.y);
                }
                if (nbv < N_NODE) {
                    float2 hv = *(const float2*)(h + nbv * HID + c);
                    *(float2*)(out_h + nbv * HID + c) =
                        make_float2(acc[mt][nb][2] + b0 + hv.x,
                                    acc[mt][nb][3] + b1 + hv.y);
                }
            }
        }
    }
    // ---- coord epilogue ----
    for (int idx = tid; idx < MN * 12; idx += NTHREADS) {
        int r = idx / 12, d = idx % 12;
        int n = nb0 + r;
        if (n < N_NODE) {
            float cnt = fmaxf(g_cnt[n], 1.0f);
            out_coord[n * 12 + d] = coord[n * 12 + d] + g_agg[n * 12 + d] / cnt;
        }
    }
}

// ============================================================================
extern "C" void kernel_launch(void* const* d_in, const int* in_sizes, int n_in,
                              void* d_out, int out_size)
{
    const float* h      = (const float*)d_in[0];
    const float* coord  = (const float*)d_in[1];
    const int*   row    = (const int*)d_in[2];
    const int*   col    = (const int*)d_in[3];
    const float* e_w1   = (const float*)d_in[4];
    const float* e_b1   = (const float*)d_in[5];
    const float* e_w2   = (const float*)d_in[6];
    const float* e_b2   = (const float*)d_in[7];
    const float* c_w1   = (const float*)d_in[8];
    const float* c_b1   = (const float*)d_in[9];
    const float* c_wout = (const float*)d_in[10];
    const float* n_w1   = (const float*)d_in[11];
    const float* n_b1   = (const float*)d_in[12];
    const float* n_w2   = (const float*)d_in[13];
    const float* n_b2   = (const float*)d_in[14];

    float* out_h     = (float*)d_out;
    float* out_coord = out_h + N_NODE * HID;

    void *p_sumsq, *p_nagg, *p_agg, *p_cnt;
    cudaGetSymbolAddress(&p_sumsq, g_sumsq);
    cudaGetSymbolAddress(&p_nagg,  g_nagg);
    cudaGetSymbolAddress(&p_agg,   g_agg);
    cudaGetSymbolAddress(&p_cnt,   g_cnt);
    cudaMemsetAsync(p_sumsq, 0, 32 * sizeof(float));
    cudaMemsetAsync(p_nagg,  0, N_NODE * HID * sizeof(float));
    cudaMemsetAsync(p_agg,   0, N_NODE * 12 * sizeof(float));
    cudaMemsetAsync(p_cnt,   0, N_NODE * sizeof(float));

    cudaFuncSetAttribute(edge_kernel, cudaFuncAttributeMaxDynamicSharedMemorySize,
                         SMEM_EDGE_BYTES);
    cudaFuncSetAttribute(node_kernel, cudaFuncAttributeMaxDynamicSharedMemorySize,
                         SMEM_NODE_BYTES);

    prep_sumsq_kernel<<<PREP_BLOCKS + SUMSQ_BLOCKS, 256>>>(
        e_w1, e_w2, c_w1, n_w1, n_w2, coord, row, col);
    edge_kernel<<<EGRID, ETHREADS, SMEM_EDGE_BYTES>>>(
        h, coord, row, col, e_b1, e_b2, c_b1, c_wout);
    node_kernel<<<(N_NODE + MN - 1) / MN, NTHREADS, SMEM_NODE_BYTES>>>(
        h, coord, n_b1, n_b2, out_h, out_coord);
}

// round 15
// speedup vs baseline: 1.4380x; 1.4380x over previous
#include <cuda_runtime.h>
#include <cuda_fp16.h>
#include <math.h>
#include <stdint.h>

#define N_NODE 10000
#define N_EDGE 320000
#define HID    128
#define NC     4

// ---------------- edge kernel geometry (ME=128, 512 thr, occ 2) ------------
#define ME      128           // edges per CTA
#define ETHREADS 512
#define LDA_B   656           // A row stride bytes
#define LDB_B   272           // B row stride bytes (136 fp16)
#define CHB     8704          // B chunk: 32 k-rows * 272 B
#define A_OFF   0             // fp16 A image: 128*656 = 83968 B
#define B_OFF   83968         // two ping-pong chunks: 2*8704 = 17408
#define OF_ROW  101376
#define OF_COL  101888
#define OF_INV  102400
#define OF_BIAS 102528
#define OF_CW   103040        // transposed c_wout: 4 x 136 fp32 = 2176 B
#define OF_CD   105216        // coord_diff: 128*12*4 = 6144 B
#define SMEM_EDGE_BYTES 111360

// ---------------- node kernel geometry (64 rows/CTA, 256 thr, occ 3) -------
#define NTHREADS 256
#define MN      64
#define NA_OFF  0             // 64*656 = 41984
#define NB_OFF  41984
#define NOF_BIAS 59392
#define SMEM_NODE_BYTES 60544

// ---------------- scratch ----------------
__device__ float g_sumsq[32];
__device__ float g_nagg[N_NODE * HID];
__device__ float g_agg[N_NODE * NC * 3];
__device__ float g_cnt[N_NODE];
// weight images: [K x 128] fp16, row stride 272 B
__device__ __align__(16) unsigned char g_w1t[288 * LDB_B];
__device__ __align__(16) unsigned char g_w2t[128 * LDB_B];
__device__ __align__(16) unsigned char g_w3t[128 * LDB_B];
__device__ __align__(16) unsigned char g_nw1t[256 * LDB_B];
__device__ __align__(16) unsigned char g_nw2t[128 * LDB_B];

__device__ __forceinline__ float silu_f(float x) {
    return __fdividef(x, 1.0f + __expf(-x));
}

__device__ __forceinline__ uint32_t smem_to_u32(const void* p) {
    uint32_t a;
    asm("{ .reg .u64 t; cvta.to.shared.u64 t, %1; cvt.u32.u64 %0, t; }" : "=r"(a) : "l"(p));
    return a;
}
__device__ __forceinline__ void ldm_x4(uint32_t (&r)[4], uint32_t addr) {
    asm volatile("ldmatrix.sync.aligned.m8n8.x4.shared.b16 {%0,%1,%2,%3}, [%4];"
                 : "=r"(r[0]), "=r"(r[1]), "=r"(r[2]), "=r"(r[3]) : "r"(addr));
}
__device__ __forceinline__ void ldm_x4_t(uint32_t (&r)[4], uint32_t addr) {
    asm volatile("ldmatrix.sync.aligned.m8n8.x4.trans.shared.b16 {%0,%1,%2,%3}, [%4];"
                 : "=r"(r[0]), "=r"(r[1]), "=r"(r[2]), "=r"(r[3]) : "r"(addr));
}
__device__ __forceinline__ void mma_f16(float (&d)[4], const uint32_t (&a)[4],
                                        uint32_t b0, uint32_t b1) {
    asm volatile("mma.sync.aligned.m16n8k16.row.col.f32.f16.f16.f32 "
                 "{%0,%1,%2,%3}, {%4,%5,%6,%7}, {%8,%9}, {%0,%1,%2,%3};"
                 : "+f"(d[0]), "+f"(d[1]), "+f"(d[2]), "+f"(d[3])
                 : "r"(a[0]), "r"(a[1]), "r"(a[2]), "r"(a[3]), "r"(b0), "r"(b1));
}
__device__ __forceinline__ void cp_async16(uint32_t dst, const void* src) {
    asm volatile("cp.async.cg.shared.global [%0], [%1], 16;" :: "r"(dst), "l"(src));
}
#define CP_COMMIT() asm volatile("cp.async.commit_group;" ::: "memory")
#define CP_WAIT0()  asm volatile("cp.async.wait_group 0;" ::: "memory")

__device__ __forceinline__ uint32_t pack2h(float a, float b) {
    __half2 t = __floats2half2_rn(a, b);
    return *reinterpret_cast<uint32_t*>(&t);
}
__device__ __forceinline__ void store4A(unsigned char* sm, int e, int col, float4 v) {
    uint32_t off = (uint32_t)(e * LDA_B + col * 2);
    *(uint2*)(sm + off) = make_uint2(pack2h(v.x, v.y), pack2h(v.z, v.w));
}

// ============================================================================
// Fused prep (weights -> fp16 images) + sumsq (2-edge ILP version).
// ============================================================================
#define PREP_BLOCKS  464
#define SUMSQ_BLOCKS 592
#define SSTRIDE (SUMSQ_BLOCKS * 256)

__device__ __forceinline__ void sumsq_accum(float (&p)[32],
                                            const float* __restrict__ coord,
                                            int ri, int ci)
{
    const float4* c4i = (const float4*)(coord + ri * 12);
    const float4* c4j = (const float4*)(coord + ci * 12);
    float4 i0 = c4i[0], i1 = c4i[1], i2 = c4i[2];
    float4 j0 = c4j[0], j1 = c4j[1], j2 = c4j[2];
    float a[12] = {i0.x,i0.y,i0.z,i0.w,i1.x,i1.y,i1.z,i1.w,i2.x,i2.y,i2.z,i2.w};
    float b[12] = {j0.x,j0.y,j0.z,j0.w,j1.x,j1.y,j1.z,j1.w,j2.x,j2.y,j2.z,j2.w};
    float d[12];
#pragma unroll
    for (int i = 0; i < 12; i++) d[i] = a[i] - b[i];
#pragma unroll
    for (int c = 0; c < 4; c++) {
#pragma unroll
        for (int f = 0; f < 4; f++) {
            float r = d[c*3+0]*d[f*3+0] + d[c*3+1]*d[f*3+1] + d[c*3+2]*d[f*3+2];
            float dx = a[c*3+0]-b[f*3+0], dy = a[c*3+1]-b[f*3+1], dz = a[c*3+2]-b[f*3+2];
            float d2 = dx*dx + dy*dy + dz*dz;
            p[c*8 + f]     += r * r;
            p[c*8 + 4 + f] += d2;
        }
    }
}

__global__ void prep_sumsq_kernel(const float* __restrict__ w1,
                                  const float* __restrict__ w2,
                                  const float* __restrict__ w3,
                                  const float* __restrict__ nw1,
                                  const float* __restrict__ nw2,
                                  const float* __restrict__ coord,
                                  const int* __restrict__ row,
                                  const int* __restrict__ col)
{
    int tid = threadIdx.x;
    if (blockIdx.x < PREP_BLOCKS) {
        int idx = blockIdx.x * 256 + tid;
        const float* W; unsigned char* dst; int r;
        if (idx < 36864)       { W = w1;  dst = g_w1t;  r = idx; }
        else if (idx < 53248)  { W = w2;  dst = g_w2t;  r = idx - 36864; }
        else if (idx < 69632)  { W = w3;  dst = g_w3t;  r = idx - 53248; }
        else if (idx < 102400) { W = nw1; dst = g_nw1t; r = idx - 69632; }
        else if (idx < 118784) { W = nw2; dst = g_nw2t; r = idx - 102400; }
        else return;
        int kk = r >> 7, n = r & 127;
        *(__half*)(dst + kk * LDB_B + n * 2) = __float2half_rn(W[kk * 128 + n]);
        return;
    }
    __shared__ float s_sum[32];
    if (tid < 32) s_sum[tid] = 0.0f;
    __syncthreads();
    float p[32];
#pragma unroll
    for (int i = 0; i < 32; i++) p[i] = 0.0f;
    int bid = blockIdx.x - PREP_BLOCKS;
    for (int e = bid * 256 + tid; e < N_EDGE; e += 2 * SSTRIDE) {
        int e2 = e + SSTRIDE;
        // issue all index loads first (overlap the two dependent chains)
        int r1 = row[e], c1 = col[e];
        int r2 = 0, c2 = 0;
        bool have2 = (e2 < N_EDGE);
        if (have2) { r2 = row[e2]; c2 = col[e2]; }
        sumsq_accum(p, coord, r1, c1);
        if (have2) sumsq_accum(p, coord, r2, c2);
    }
#pragma unroll
    for (int i = 0; i < 32; i++) atomicAdd(&s_sum[i], p[i]);
    __syncthreads();
    if (tid < 32) atomicAdd(&g_sumsq[tid], s_sum[tid]);
}

// ============================================================================
// cp.async staging of one 32-row B chunk (8704 B = 544 x 16B), 512 threads
// ============================================================================
__device__ __forceinline__ void cp_issue_chunk(uint32_t dst,
                                               const unsigned char* __restrict__ src,
                                               int tid)
{
#pragma unroll
    for (int i = 0; i < 2; i++) {
        int idx = tid + i * ETHREADS;
        if (idx < CHB / 16) cp_async16(dst + idx * 16, src + idx * 16);
    }
}

// ============================================================================
// EDGE GEMM: 16 warps in 4x4 grid, warp tile 32 rows x 32 cols, acc[2][4][4].
// cp.async double-buffered B (32-row chunks), one barrier per chunk.
// ============================================================================
template <int KTOT>
__device__ __forceinline__ void run_gemm_e(
    unsigned char* sm, uint32_t smem_base, float (&acc)[2][4][4],
    int a_col_base, const unsigned char* __restrict__ wsrc,
    int tid, int lane, int r0, int n0)
{
#pragma unroll
    for (int mt = 0; mt < 2; mt++)
#pragma unroll
        for (int nb = 0; nb < 4; nb++)
#pragma unroll
            for (int i = 0; i < 4; i++) acc[mt][nb][i] = 0.0f;

    constexpr int NCH = KTOT / 32;
    cp_issue_chunk(smem_base + B_OFF, wsrc, tid);
    CP_COMMIT();

#pragma unroll
    for (int c = 0; c < NCH; c++) {
        CP_WAIT0();
        __syncthreads();        // chunk c visible; all warps done with buf (c+1)&1
        if (c + 1 < NCH) {
            cp_issue_chunk(smem_base + B_OFF + ((c + 1) & 1) * CHB,
                           wsrc + (c + 1) * CHB, tid);
            CP_COMMIT();
        }
        uint32_t bbase = smem_base + B_OFF + (c & 1) * CHB;
#pragma unroll
        for (int ks = 0; ks < 2; ks++) {
            int kcol = a_col_base + c * 32 + ks * 16;
            uint32_t ah[2][4];
            uint32_t a_off = (uint32_t)((r0 + (lane & 15)) * LDA_B + (kcol + (lane >> 4) * 8) * 2);
            ldm_x4(ah[0], smem_base + A_OFF + a_off);
            ldm_x4(ah[1], smem_base + A_OFF + a_off + 16 * LDA_B);
            uint32_t bh[2][4];
            uint32_t b_off = (uint32_t)((ks * 16 + (lane & 15)) * LDB_B + (n0 + (lane >> 4) * 8) * 2);
#pragma unroll
            for (int nt = 0; nt < 2; nt++)
                ldm_x4_t(bh[nt], bbase + b_off + nt * 32);
#pragma unroll
            for (int mt = 0; mt < 2; mt++)
#pragma unroll
                for (int nt = 0; nt < 2; nt++) {
                    mma_f16(acc[mt][2*nt],   ah[mt], bh[nt][0], bh[nt][1]);
                    mma_f16(acc[mt][2*nt+1], ah[mt], bh[nt][2], bh[nt][3]);
                }
        }
    }
    __syncthreads();   // last chunk's MMAs complete in all warps before A reuse
}

// bias + silu + fp16-store to A cols [dstbase, dstbase+128)
__device__ __forceinline__ void epi_store_e(
    unsigned char* sm, float (&acc)[2][4][4], const float* __restrict__ SBIAS,
    int dstbase, int lane, int r0, int n0)
{
#pragma unroll
    for (int mt = 0; mt < 2; mt++) {
        int ra = r0 + mt * 16 + (lane >> 2);
        int rb = ra + 8;
#pragma unroll
        for (int nb = 0; nb < 4; nb++) {
            int c = n0 + nb * 8 + (lane & 3) * 2;
            float b0 = SBIAS[c], b1 = SBIAS[c + 1];
            float v0 = silu_f(acc[mt][nb][0] + b0);
            float v1 = silu_f(acc[mt][nb][1] + b1);
            float v2 = silu_f(acc[mt][nb][2] + b0);
            float v3 = silu_f(acc[mt][nb][3] + b1);
            *(uint32_t*)(sm + ra * LDA_B + (dstbase + c) * 2) = pack2h(v0, v1);
            *(uint32_t*)(sm + rb * LDA_B + (dstbase + c) * 2) = pack2h(v2, v3);
        }
    }
}

// ============================================================================
// Fused edge kernel: 128 edges / CTA, 512 threads, 16 warps (4x4), 2 CTAs/SM.
// ============================================================================
__global__ void __launch_bounds__(ETHREADS, 2)
edge_kernel(const float* __restrict__ h, const float* __restrict__ coord,
            const int* __restrict__ row, const int* __restrict__ col,
            const float* __restrict__ e_b1, const float* __restrict__ e_b2,
            const float* __restrict__ c_b1, const float* __restrict__ c_wout)
{
    extern __shared__ unsigned char sm[];
    const int tid  = threadIdx.x;
    const int wid  = tid >> 5;
    const int lane = tid & 31;
    const int e0   = blockIdx.x * ME;
    uint32_t smem_base = smem_to_u32(sm);

    int*   SROW  = (int*)(sm + OF_ROW);
    int*   SCOL  = (int*)(sm + OF_COL);
    float* SINV  = (float*)(sm + OF_INV);
    float* SBIAS = (float*)(sm + OF_BIAS);
    float* SCWT  = (float*)(sm + OF_CW);    // [4][136] transposed c_wout
    float* SCD   = (float*)(sm + OF_CD);

    if (tid < ME)  { SROW[tid] = row[e0 + tid]; SCOL[tid] = col[e0 + tid]; }
    if (tid < 32)  SINV[tid] = 1.0f / fmaxf(sqrtf(g_sumsq[tid]), 1e-12f);
    if (tid < 256) {   // transpose c_wout [128][4] -> SCWT [4][136]
        int k = tid >> 1, half = tid & 1;
        float2 v = ((const float2*)c_wout)[tid];
        SCWT[(half * 2 + 0) * 136 + k] = v.x;
        SCWT[(half * 2 + 1) * 136 + k] = v.y;
    }
    __syncthreads();

    // ---- gather h[row]|h[col] into A cols 0..255 (fp16) ----
#pragma unroll 4
    for (int idx = tid; idx < ME * 64; idx += ETHREADS) {
        int e = idx >> 6, p4 = idx & 63;
        int half = p4 >> 5, q = p4 & 31;
        int node = half ? SCOL[e] : SROW[e];
        float4 v = ((const float4*)(h + node * HID))[q];
        store4A(sm, e, half * 128 + q * 4, v);
    }
    // ---- rad features cols 256..287; coord_diff to SCD ----
    if (tid < ME) {
        int e = tid;
        const float4* c4i = (const float4*)(coord + SROW[e] * 12);
        const float4* c4j = (const float4*)(coord + SCOL[e] * 12);
        float4 i0 = c4i[0], i1 = c4i[1], i2 = c4i[2];
        float4 j0 = c4j[0], j1 = c4j[1], j2 = c4j[2];
        float a[12] = {i0.x,i0.y,i0.z,i0.w,i1.x,i1.y,i1.z,i1.w,i2.x,i2.y,i2.z,i2.w};
        float b[12] = {j0.x,j0.y,j0.z,j0.w,j1.x,j1.y,j1.z,j1.w,j2.x,j2.y,j2.z,j2.w};
        float d[12];
#pragma unroll
        for (int i = 0; i < 12; i++) { d[i] = a[i] - b[i]; SCD[e * 12 + i] = d[i]; }
        float radv[32];
#pragma unroll
        for (int c = 0; c < 4; c++) {
#pragma unroll
            for (int f = 0; f < 4; f++) {
                float r = d[c*3+0]*d[f*3+0] + d[c*3+1]*d[f*3+1] + d[c*3+2]*d[f*3+2];
                float dx = a[c*3+0]-b[f*3+0], dy = a[c*3+1]-b[f*3+1], dz = a[c*3+2]-b[f*3+2];
                float d2 = dx*dx + dy*dy + dz*dz;
                radv[c*8 + f]     = r * SINV[c*8 + f];
                radv[c*8 + 4 + f] = sqrtf(d2) * SINV[c*8 + 4 + f];
            }
        }
#pragma unroll
        for (int q = 0; q < 32; q += 4)
            store4A(sm, e, 256 + q, make_float4(radv[q], radv[q+1], radv[q+2], radv[q+3]));
    }

    const int wm = wid & 3, wn = wid >> 2;
    const int r0 = wm * 32, n0 = wn * 32;
    float acc[2][4][4];

    // ========== GEMM1: t1 = silu(eh @ W1 + b1) -> A cols 0..127 (K=288) ===
    if (tid < 128) SBIAS[tid] = e_b1[tid];
    run_gemm_e<288>(sm, smem_base, acc, 0, g_w1t, tid, lane, r0, n0);
    epi_store_e(sm, acc, SBIAS, 0, lane, r0, n0);
    __syncthreads();

    // ========== GEMM2: m = silu(t1 @ W2 + b2) -> A cols 128..255 ==========
    if (tid < 128) SBIAS[tid] = e_b2[tid];
    run_gemm_e<128>(sm, smem_base, acc, 0, g_w2t, tid, lane, r0, n0);
    epi_store_e(sm, acc, SBIAS, 128, lane, r0, n0);
    __syncthreads();

    // ---- nagg scatter: coalesced red.v4 from fp16 m in smem ----
#pragma unroll 4
    for (int idx = tid; idx < ME * 32; idx += ETHREADS) {
        int e = idx >> 5, q = (idx & 31) * 4;
        uint2 hv = *(const uint2*)(sm + e * LDA_B + (128 + q) * 2);
        __half2 p0 = *reinterpret_cast<__half2*>(&hv.x);
        __half2 p1 = *reinterpret_cast<__half2*>(&hv.y);
        float2 f0 = __half22float2(p0), f1 = __half22float2(p1);
        float* dst = g_nagg + (size_t)SROW[e] * HID + q;
        asm volatile("red.global.add.v4.f32 [%0], {%1,%2,%3,%4};"
                     :: "l"(dst), "f"(f0.x), "f"(f0.y), "f"(f1.x), "f"(f1.y)
                     : "memory");
    }

    // ========== GEMM3: t2 = silu(m @ c_w1 + b) -> fp32 buffer =============
    if (tid < 128) SBIAS[tid] = c_b1[tid];
    run_gemm_e<128>(sm, smem_base, acc, 128, g_w3t, tid, lane, r0, n0);
    {
        float* t2f = (float*)sm;            // [128 x 132] fp32; A done after GEMM3
#pragma unroll
        for (int mt = 0; mt < 2; mt++) {
            int ra = r0 + mt * 16 + (lane >> 2);
            int rb = ra + 8;
#pragma unroll
            for (int nb = 0; nb < 4; nb++) {
                int c = n0 + nb * 8 + (lane & 3) * 2;
                float b0 = SBIAS[c], b1 = SBIAS[c + 1];
                *(float2*)(t2f + ra * 132 + c) =
                    make_float2(silu_f(acc[mt][nb][0] + b0), silu_f(acc[mt][nb][1] + b1));
                *(float2*)(t2f + rb * 132 + c) =
                    make_float2(silu_f(acc[mt][nb][2] + b0), silu_f(acc[mt][nb][3] + b1));
            }
        }
    }
    __syncthreads();

    // ========== w = t2 @ c_wout (float4 dot); coord atomics ===============
    if (tid < ME * 4) {
        int e = tid >> 2, c = tid & 3;
        const float4* tr4 = (const float4*)((const float*)sm + e * 132);
        const float4* cw4 = (const float4*)(SCWT + c * 136);
        float w = 0.0f;
#pragma unroll
        for (int i = 0; i < 32; i++) {
            float4 t = tr4[i], uq = cw4[i];
            w += t.x * uq.x + t.y * uq.y + t.z * uq.z + t.w * uq.w;
        }
        int node = SROW[e];
        const float* cd = SCD + e * 12 + c * 3;
        atomicAdd(&g_agg[node * 12 + c * 3 + 0], cd[0] * w);
        atomicAdd(&g_agg[node * 12 + c * 3 + 1], cd[1] * w);
        atomicAdd(&g_agg[node * 12 + c * 3 + 2], cd[2] * w);
        if (c == 0) atomicAdd(&g_cnt[node], 1.0f);
    }
}

// ============================================================================
// NODE GEMM machinery (64 rows/CTA, 256 threads, 2x4 warp grid, tile 32x32)
// ============================================================================
#define NSTG 5

__device__ __forceinline__ void ld_stageN(uint4 (&stg)[NSTG],
                                          const unsigned char* __restrict__ wsrc,
                                          int byteoff, int n4, int tid)
{
    const uint4* s = (const uint4*)(wsrc + byteoff);
#pragma unroll
    for (int i = 0; i < NSTG; i++) {
        int idx = tid + i * NTHREADS;
        if (idx < n4) stg[i] = s[idx];
    }
}

template <int KTOT>
__device__ __forceinline__ void run_gemm_n(
    unsigned char* sm, uint32_t smem_base, float (&acc)[2][4][4],
    int a_col_base, const unsigned char* __restrict__ wsrc,
    int tid, int lane, int r0, int n0)
{
#pragma unroll
    for (int mt = 0; mt < 2; mt++)
#pragma unroll
        for (int nb = 0; nb < 4; nb++)
#pragma unroll
            for (int i = 0; i < 4; i++) acc[mt][nb][i] = 0.0f;

    uint4 stg[NSTG];
    constexpr int R0 = (KTOT < 64) ? KTOT : 64;
    ld_stageN(stg, wsrc, 0, R0 * 17, tid);

#pragma unroll
    for (int k0 = 0; k0 < KTOT; k0 += 64) {
        const int rows = (KTOT - k0 < 64) ? (KTOT - k0) : 64;
        const int cn4 = rows * 17;
        __syncthreads();
        {
            uint4* db = (uint4*)(sm + NB_OFF);
#pragma unroll
            for (int i = 0; i < NSTG; i++) {
                int idx = tid + i * NTHREADS;
                if (idx < cn4) db[idx] = stg[i];
            }
        }
        __syncthreads();
        if (k0 + 64 < KTOT) {
            const int nrows = (KTOT - k0 - 64 < 64) ? (KTOT - k0 - 64) : 64;
            ld_stageN(stg, wsrc, (k0 + 64) * LDB_B, nrows * 17, tid);
        }
        const int nks = rows >> 4;
#pragma unroll
        for (int ks = 0; ks < 4; ks++) {
            if (ks >= nks) break;
            int kcol = a_col_base + k0 + ks * 16;
            uint32_t ah[2][4];
            uint32_t a_off = (uint32_t)((r0 + (lane & 15)) * LDA_B + (kcol + (lane >> 4) * 8) * 2);
            ldm_x4(ah[0], smem_base + NA_OFF + a_off);
            ldm_x4(ah[1], smem_base + NA_OFF + a_off + 16 * LDA_B);
            uint32_t bh[2][4];
            uint32_t b_off = (uint32_t)((ks * 16 + (lane & 15)) * LDB_B + (n0 + (lane >> 4) * 8) * 2);
#pragma unroll
            for (int nt = 0; nt < 2; nt++)
                ldm_x4_t(bh[nt], smem_base + NB_OFF + b_off + nt * 32);
#pragma unroll
            for (int mt = 0; mt < 2; mt++)
#pragma unroll
                for (int nt = 0; nt < 2; nt++) {
                    mma_f16(acc[mt][2*nt],   ah[mt], bh[nt][0], bh[nt][1]);
                    mma_f16(acc[mt][2*nt+1], ah[mt], bh[nt][2], bh[nt][3]);
                }
        }
    }
    __syncthreads();
}

__global__ void __launch_bounds__(NTHREADS, 3)
node_kernel(const float* __restrict__ h, const float* __restrict__ coord,
            const float* __restrict__ n_b1, const float* __restrict__ n_b2,
            float* __restrict__ out_h, float* __restrict__ out_coord)
{
    extern __shared__ unsigned char sm[];
    const int tid  = threadIdx.x;
    const int wid  = tid >> 5;
    const int lane = tid & 31;
    const int nb0  = blockIdx.x * MN;
    uint32_t smem_base = smem_to_u32(sm);
    float* SBIAS = (float*)(sm + NOF_BIAS);

    // ---- gather h[n] | nagg[n] into A cols 0..255 (fp16) ----
#pragma unroll 4
    for (int idx = tid; idx < MN * 64; idx += NTHREADS) {
        int r = idx >> 6, p4 = idx & 63;
        int half = p4 >> 5, q = p4 & 31;
        int n = nb0 + r;
        float4 v = make_float4(0.f, 0.f, 0.f, 0.f);
        if (n < N_NODE)
            v = half ? ((const float4*)(g_nagg + n * HID))[q]
                     : ((const float4*)(h + n * HID))[q];
        store4A(sm, r, half * 128 + q * 4, v);
    }

    const int wm = wid & 1, wn = wid >> 1;
    const int r0 = wm * 32, n0 = wn * 32;
    float acc[2][4][4];

    // ========== GEMM1: t = silu(nin @ nW1 + b1) -> A cols 0..127 ==========
    if (tid < 128) SBIAS[tid] = n_b1[tid];
    run_gemm_n<256>(sm, smem_base, acc, 0, g_nw1t, tid, lane, r0, n0);
    {
#pragma unroll
        for (int mt = 0; mt < 2; mt++) {
            int ra = r0 + mt * 16 + (lane >> 2);
            int rb = ra + 8;
#pragma unroll
            for (int nb = 0; nb < 4; nb++) {
                int c = n0 + nb * 8 + (lane & 3) * 2;
                float b0 = SBIAS[c], b1 = SBIAS[c + 1];
                *(uint32_t*)(sm + ra * LDA_B + c * 2) =
                    pack2h(silu_f(acc[mt][nb][0] + b0), silu_f(acc[mt][nb][1] + b1));
                *(uint32_t*)(sm + rb * LDA_B + c * 2) =
                    pack2h(silu_f(acc[mt][nb][2] + b0), silu_f(acc[mt][nb][3] + b1));
            }
        }
    }
    __syncthreads();

    // ========== GEMM2: hn = t @ nW2 + b2 ; out_h = h + hn =================
    if (tid < 128) SBIAS[tid] = n_b2[tid];
    run_gemm_n<128>(sm, smem_base, acc, 0, g_nw2t, tid, lane, r0, n0);
    {
#pragma unroll
        for (int mt = 0; mt < 2; mt++) {
            int ra = r0 + mt * 16 + (lane >> 2);
            int rb = ra + 8;
            int na = nb0 + ra, nbv = nb0 + rb;
#pragma unroll
            for (int nb = 0; nb < 4; nb++) {
                int c = n0 + nb * 8 + (lane & 3) * 2;
                float b0 = SBIAS[c], b1 = SBIAS[c + 1];
                if (na < N_NODE) {
                    float2 hv = *(const float2*)(h + na * HID + c);
                    *(float2*)(out_h + na * HID + c) =
                        make_float2(acc[mt][nb][0] + b0 + hv.x,
                                    acc[mt][nb][1] + b1 + hv.y);
                }
                if (nbv < N_NODE) {
                    float2 hv = *(const float2*)(h + nbv * HID + c);
                    *(float2*)(out_h + nbv * HID + c) =
                        make_float2(acc[mt][nb][2] + b0 + hv.x,
                                    acc[mt][nb][3] + b1 + hv.y);
                }
            }
        }
    }
    // ---- coord epilogue ----
    for (int idx = tid; idx < MN * 12; idx += NTHREADS) {
        int r = idx / 12, d = idx % 12;
        int n = nb0 + r;
        if (n < N_NODE) {
            float cnt = fmaxf(g_cnt[n], 1.0f);
            out_coord[n * 12 + d] = coord[n * 12 + d] + g_agg[n * 12 + d] / cnt;
        }
    }
}

// ============================================================================
extern "C" void kernel_launch(void* const* d_in, const int* in_sizes, int n_in,
                              void* d_out, int out_size)
{
    const float* h      = (const float*)d_in[0];
    const float* coord  = (const float*)d_in[1];
    const int*   row    = (const int*)d_in[2];
    const int*   col    = (const int*)d_in[3];
    const float* e_w1   = (const float*)d_in[4];
    const float* e_b1   = (const float*)d_in[5];
    const float* e_w2   = (const float*)d_in[6];
    const float* e_b2   = (const float*)d_in[7];
    const float* c_w1   = (const float*)d_in[8];
    const float* c_b1   = (const float*)d_in[9];
    const float* c_wout = (const float*)d_in[10];
    const float* n_w1   = (const float*)d_in[11];
    const float* n_b1   = (const float*)d_in[12];
    const float* n_w2   = (const float*)d_in[13];
    const float* n_b2   = (const float*)d_in[14];

    float* out_h     = (float*)d_out;
    float* out_coord = out_h + N_NODE * HID;

    void *p_sumsq, *p_nagg, *p_agg, *p_cnt;
    cudaGetSymbolAddress(&p_sumsq, g_sumsq);
    cudaGetSymbolAddress(&p_nagg,  g_nagg);
    cudaGetSymbolAddress(&p_agg,   g_agg);
    cudaGetSymbolAddress(&p_cnt,   g_cnt);
    cudaMemsetAsync(p_sumsq, 0, 32 * sizeof(float));
    cudaMemsetAsync(p_nagg,  0, N_NODE * HID * sizeof(float));
    cudaMemsetAsync(p_agg,   0, N_NODE * 12 * sizeof(float));
    cudaMemsetAsync(p_cnt,   0, N_NODE * sizeof(float));

    cudaFuncSetAttribute(edge_kernel, cudaFuncAttributeMaxDynamicSharedMemorySize,
                         SMEM_EDGE_BYTES);
    cudaFuncSetAttribute(node_kernel, cudaFuncAttributeMaxDynamicSharedMemorySize,
                         SMEM_NODE_BYTES);

    prep_sumsq_kernel<<<PREP_BLOCKS + SUMSQ_BLOCKS, 256>>>(
        e_w1, e_w2, c_w1, n_w1, n_w2, coord, row, col);
    edge_kernel<<<N_EDGE / ME, ETHREADS, SMEM_EDGE_BYTES>>>(
        h, coord, row, col, e_b1, e_b2, c_b1, c_wout);
    node_kernel<<<(N_NODE + MN - 1) / MN, NTHREADS, SMEM_NODE_BYTES>>>(
        h, coord, n_b1, n_b2, out_h, out_coord);
}

// round 16
// speedup vs baseline: 1.7295x; 1.2027x over previous
#include <cuda_runtime.h>
#include <cuda_fp16.h>
#include <math.h>
#include <stdint.h>

#define N_NODE 10000
#define N_EDGE 320000
#define HID    128
#define NC     4

// ---------------- edge kernel geometry (ME=128, 512 thr, occ 2) ------------
#define ME      128           // edges per CTA
#define ETHREADS 512
#define LDA_B   656           // A row stride bytes
#define LDB_B   272           // B row stride bytes (136 fp16)
#define CHB     8704          // B chunk: 32 k-rows * 272 B
#define A_OFF   0             // fp16 A image: 128*656 = 83968 B
#define B_OFF   83968         // two ping-pong chunks: 2*8704 = 17408
#define OF_ROW  101376
#define OF_COL  101888
#define OF_INV  102400
#define OF_BIAS 102528
#define OF_CW   103040        // transposed c_wout: 4 x 136 fp32 = 2176 B
#define OF_CD   105216        // coord_diff: 128*12*4 = 6144 B
#define SMEM_EDGE_BYTES 111360

// ---------------- node kernel geometry (64 rows/CTA, 256 thr, occ 3) -------
#define NTHREADS 256
#define MN      64
#define NA_OFF  0             // 64*656 = 41984
#define NB_OFF  41984
#define NOF_BIAS 59392
#define SMEM_NODE_BYTES 60544

// ---------------- scratch ----------------
__device__ float g_sumsq[32];
__device__ float g_nagg[N_NODE * HID];
__device__ float g_agg[N_NODE * NC * 3];
__device__ float g_cnt[N_NODE];
// weight images: [K x 128] fp16, row stride 272 B
__device__ __align__(16) unsigned char g_w1t[288 * LDB_B];
__device__ __align__(16) unsigned char g_w2t[128 * LDB_B];
__device__ __align__(16) unsigned char g_w3t[128 * LDB_B];
__device__ __align__(16) unsigned char g_nw1t[256 * LDB_B];
__device__ __align__(16) unsigned char g_nw2t[128 * LDB_B];

__device__ __forceinline__ float silu_f(float x) {
    return __fdividef(x, 1.0f + __expf(-x));
}

__device__ __forceinline__ uint32_t smem_to_u32(const void* p) {
    uint32_t a;
    asm("{ .reg .u64 t; cvta.to.shared.u64 t, %1; cvt.u32.u64 %0, t; }" : "=r"(a) : "l"(p));
    return a;
}
__device__ __forceinline__ void ldm_x4(uint32_t (&r)[4], uint32_t addr) {
    asm volatile("ldmatrix.sync.aligned.m8n8.x4.shared.b16 {%0,%1,%2,%3}, [%4];"
                 : "=r"(r[0]), "=r"(r[1]), "=r"(r[2]), "=r"(r[3]) : "r"(addr));
}
__device__ __forceinline__ void ldm_x4_t(uint32_t (&r)[4], uint32_t addr) {
    asm volatile("ldmatrix.sync.aligned.m8n8.x4.trans.shared.b16 {%0,%1,%2,%3}, [%4];"
                 : "=r"(r[0]), "=r"(r[1]), "=r"(r[2]), "=r"(r[3]) : "r"(addr));
}
__device__ __forceinline__ void mma_f16(float (&d)[4], const uint32_t (&a)[4],
                                        uint32_t b0, uint32_t b1) {
    asm volatile("mma.sync.aligned.m16n8k16.row.col.f32.f16.f16.f32 "
                 "{%0,%1,%2,%3}, {%4,%5,%6,%7}, {%8,%9}, {%0,%1,%2,%3};"
                 : "+f"(d[0]), "+f"(d[1]), "+f"(d[2]), "+f"(d[3])
                 : "r"(a[0]), "r"(a[1]), "r"(a[2]), "r"(a[3]), "r"(b0), "r"(b1));
}
__device__ __forceinline__ void cp_async16(uint32_t dst, const void* src) {
    asm volatile("cp.async.cg.shared.global [%0], [%1], 16;" :: "r"(dst), "l"(src));
}
#define CP_COMMIT() asm volatile("cp.async.commit_group;" ::: "memory")
#define CP_WAIT0()  asm volatile("cp.async.wait_group 0;" ::: "memory")

__device__ __forceinline__ uint32_t pack2h(float a, float b) {
    __half2 t = __floats2half2_rn(a, b);
    return *reinterpret_cast<uint32_t*>(&t);
}
__device__ __forceinline__ void store4A(unsigned char* sm, int e, int col, float4 v) {
    uint32_t off = (uint32_t)(e * LDA_B + col * 2);
    *(uint2*)(sm + off) = make_uint2(pack2h(v.x, v.y), pack2h(v.z, v.w));
}

// ============================================================================
// Fused prep (4 elems/thread) + sumsq (4-5 edges/thread ILP).
// ============================================================================
#define PREP_BLOCKS  116
#define PREP_STRIDE  (PREP_BLOCKS * 256)     // 29696; 4*29696 = 118784 exact
#define SUMSQ_BLOCKS 296
#define SSTRIDE      (SUMSQ_BLOCKS * 256)    // 75776

__device__ __forceinline__ void prep_decode(int idx, const float* w1, const float* w2,
                                            const float* w3, const float* nw1,
                                            const float* nw2,
                                            const float** W, unsigned char** dst, int* r)
{
    if (idx < 36864)       { *W = w1;  *dst = g_w1t;  *r = idx; }
    else if (idx < 53248)  { *W = w2;  *dst = g_w2t;  *r = idx - 36864; }
    else if (idx < 69632)  { *W = w3;  *dst = g_w3t;  *r = idx - 53248; }
    else if (idx < 102400) { *W = nw1; *dst = g_nw1t; *r = idx - 69632; }
    else                   { *W = nw2; *dst = g_nw2t; *r = idx - 102400; }
}

__device__ __forceinline__ void sumsq_accum(float (&p)[32],
                                            const float* __restrict__ coord,
                                            int ri, int ci)
{
    const float4* c4i = (const float4*)(coord + ri * 12);
    const float4* c4j = (const float4*)(coord + ci * 12);
    float4 i0 = c4i[0], i1 = c4i[1], i2 = c4i[2];
    float4 j0 = c4j[0], j1 = c4j[1], j2 = c4j[2];
    float a[12] = {i0.x,i0.y,i0.z,i0.w,i1.x,i1.y,i1.z,i1.w,i2.x,i2.y,i2.z,i2.w};
    float b[12] = {j0.x,j0.y,j0.z,j0.w,j1.x,j1.y,j1.z,j1.w,j2.x,j2.y,j2.z,j2.w};
    float d[12];
#pragma unroll
    for (int i = 0; i < 12; i++) d[i] = a[i] - b[i];
#pragma unroll
    for (int c = 0; c < 4; c++) {
#pragma unroll
        for (int f = 0; f < 4; f++) {
            float r = d[c*3+0]*d[f*3+0] + d[c*3+1]*d[f*3+1] + d[c*3+2]*d[f*3+2];
            float dx = a[c*3+0]-b[f*3+0], dy = a[c*3+1]-b[f*3+1], dz = a[c*3+2]-b[f*3+2];
            float d2 = dx*dx + dy*dy + dz*dz;
            p[c*8 + f]     += r * r;
            p[c*8 + 4 + f] += d2;
        }
    }
}

__global__ void prep_sumsq_kernel(const float* __restrict__ w1,
                                  const float* __restrict__ w2,
                                  const float* __restrict__ w3,
                                  const float* __restrict__ nw1,
                                  const float* __restrict__ nw2,
                                  const float* __restrict__ coord,
                                  const int* __restrict__ row,
                                  const int* __restrict__ col)
{
    int tid = threadIdx.x;
    if (blockIdx.x < PREP_BLOCKS) {
        int base = blockIdx.x * 256 + tid;
        const float* W[4]; unsigned char* dst[4]; int r[4];
#pragma unroll
        for (int j = 0; j < 4; j++)
            prep_decode(base + j * PREP_STRIDE, w1, w2, w3, nw1, nw2,
                        &W[j], &dst[j], &r[j]);
        float v[4];
#pragma unroll
        for (int j = 0; j < 4; j++)
            v[j] = W[j][(r[j] >> 7) * 128 + (r[j] & 127)];
#pragma unroll
        for (int j = 0; j < 4; j++)
            *(__half*)(dst[j] + (r[j] >> 7) * LDB_B + (r[j] & 127) * 2) =
                __float2half_rn(v[j]);
        return;
    }
    // ---- sumsq: 4 guaranteed edges + optional 5th per thread ----
    __shared__ float s_sum[32];
    if (tid < 32) s_sum[tid] = 0.0f;
    __syncthreads();
    float p[32];
#pragma unroll
    for (int i = 0; i < 32; i++) p[i] = 0.0f;
    int bid = blockIdx.x - PREP_BLOCKS;
    int e0 = bid * 256 + tid;                 // < 75776; e0..e0+3*S all < N_EDGE
    int r0 = row[e0],              c0 = col[e0];
    int r1 = row[e0 + SSTRIDE],    c1 = col[e0 + SSTRIDE];
    int r2 = row[e0 + 2*SSTRIDE],  c2 = col[e0 + 2*SSTRIDE];
    int r3 = row[e0 + 3*SSTRIDE],  c3 = col[e0 + 3*SSTRIDE];
    int e4 = e0 + 4*SSTRIDE;
    bool h4 = (e4 < N_EDGE);
    int r4 = 0, c4 = 0;
    if (h4) { r4 = row[e4]; c4 = col[e4]; }
    sumsq_accum(p, coord, r0, c0);
    sumsq_accum(p, coord, r1, c1);
    sumsq_accum(p, coord, r2, c2);
    sumsq_accum(p, coord, r3, c3);
    if (h4) sumsq_accum(p, coord, r4, c4);
#pragma unroll
    for (int i = 0; i < 32; i++) atomicAdd(&s_sum[i], p[i]);
    __syncthreads();
    if (tid < 32) atomicAdd(&g_sumsq[tid], s_sum[tid]);
}

// ============================================================================
// cp.async staging of one 32-row B chunk (8704 B = 544 x 16B), 512 threads
// ============================================================================
__device__ __forceinline__ void cp_issue_chunk(uint32_t dst,
                                               const unsigned char* __restrict__ src,
                                               int tid)
{
#pragma unroll
    for (int i = 0; i < 2; i++) {
        int idx = tid + i * ETHREADS;
        if (idx < CHB / 16) cp_async16(dst + idx * 16, src + idx * 16);
    }
}

// ============================================================================
// EDGE GEMM: 16 warps in 4x4 grid, warp tile 32 rows x 32 cols, acc[2][4][4].
// cp.async double-buffered B (32-row chunks), one barrier per chunk.
// ============================================================================
template <int KTOT>
__device__ __forceinline__ void run_gemm_e(
    unsigned char* sm, uint32_t smem_base, float (&acc)[2][4][4],
    int a_col_base, const unsigned char* __restrict__ wsrc,
    int tid, int lane, int r0, int n0)
{
#pragma unroll
    for (int mt = 0; mt < 2; mt++)
#pragma unroll
        for (int nb = 0; nb < 4; nb++)
#pragma unroll
            for (int i = 0; i < 4; i++) acc[mt][nb][i] = 0.0f;

    constexpr int NCH = KTOT / 32;
    cp_issue_chunk(smem_base + B_OFF, wsrc, tid);
    CP_COMMIT();

#pragma unroll
    for (int c = 0; c < NCH; c++) {
        CP_WAIT0();
        __syncthreads();        // chunk c visible; all warps done with buf (c+1)&1
        if (c + 1 < NCH) {
            cp_issue_chunk(smem_base + B_OFF + ((c + 1) & 1) * CHB,
                           wsrc + (c + 1) * CHB, tid);
            CP_COMMIT();
        }
        uint32_t bbase = smem_base + B_OFF + (c & 1) * CHB;
#pragma unroll
        for (int ks = 0; ks < 2; ks++) {
            int kcol = a_col_base + c * 32 + ks * 16;
            uint32_t ah[2][4];
            uint32_t a_off = (uint32_t)((r0 + (lane & 15)) * LDA_B + (kcol + (lane >> 4) * 8) * 2);
            ldm_x4(ah[0], smem_base + A_OFF + a_off);
            ldm_x4(ah[1], smem_base + A_OFF + a_off + 16 * LDA_B);
            uint32_t bh[2][4];
            uint32_t b_off = (uint32_t)((ks * 16 + (lane & 15)) * LDB_B + (n0 + (lane >> 4) * 8) * 2);
#pragma unroll
            for (int nt = 0; nt < 2; nt++)
                ldm_x4_t(bh[nt], bbase + b_off + nt * 32);
#pragma unroll
            for (int mt = 0; mt < 2; mt++)
#pragma unroll
                for (int nt = 0; nt < 2; nt++) {
                    mma_f16(acc[mt][2*nt],   ah[mt], bh[nt][0], bh[nt][1]);
                    mma_f16(acc[mt][2*nt+1], ah[mt], bh[nt][2], bh[nt][3]);
                }
        }
    }
    __syncthreads();   // last chunk's MMAs complete in all warps before A reuse
}

// bias + silu + fp16-store to A cols [dstbase, dstbase+128)
__device__ __forceinline__ void epi_store_e(
    unsigned char* sm, float (&acc)[2][4][4], const float* __restrict__ SBIAS,
    int dstbase, int lane, int r0, int n0)
{
#pragma unroll
    for (int mt = 0; mt < 2; mt++) {
        int ra = r0 + mt * 16 + (lane >> 2);
        int rb = ra + 8;
#pragma unroll
        for (int nb = 0; nb < 4; nb++) {
            int c = n0 + nb * 8 + (lane & 3) * 2;
            float b0 = SBIAS[c], b1 = SBIAS[c + 1];
            float v0 = silu_f(acc[mt][nb][0] + b0);
            float v1 = silu_f(acc[mt][nb][1] + b1);
            float v2 = silu_f(acc[mt][nb][2] + b0);
            float v3 = silu_f(acc[mt][nb][3] + b1);
            *(uint32_t*)(sm + ra * LDA_B + (dstbase + c) * 2) = pack2h(v0, v1);
            *(uint32_t*)(sm + rb * LDA_B + (dstbase + c) * 2) = pack2h(v2, v3);
        }
    }
}

// ============================================================================
// Fused edge kernel: 128 edges / CTA, 512 threads, 16 warps (4x4), 2 CTAs/SM.
// ============================================================================
__global__ void __launch_bounds__(ETHREADS, 2)
edge_kernel(const float* __restrict__ h, const float* __restrict__ coord,
            const int* __restrict__ row, const int* __restrict__ col,
            const float* __restrict__ e_b1, const float* __restrict__ e_b2,
            const float* __restrict__ c_b1, const float* __restrict__ c_wout)
{
    extern __shared__ unsigned char sm[];
    const int tid  = threadIdx.x;
    const int wid  = tid >> 5;
    const int lane = tid & 31;
    const int e0   = blockIdx.x * ME;
    uint32_t smem_base = smem_to_u32(sm);

    int*   SROW  = (int*)(sm + OF_ROW);
    int*   SCOL  = (int*)(sm + OF_COL);
    float* SINV  = (float*)(sm + OF_INV);
    float* SBIAS = (float*)(sm + OF_BIAS);
    float* SCWT  = (float*)(sm + OF_CW);    // [4][136] transposed c_wout
    float* SCD   = (float*)(sm + OF_CD);

    if (tid < ME)  { SROW[tid] = row[e0 + tid]; SCOL[tid] = col[e0 + tid]; }
    if (tid < 32)  SINV[tid] = 1.0f / fmaxf(sqrtf(g_sumsq[tid]), 1e-12f);
    if (tid < 256) {   // transpose c_wout [128][4] -> SCWT [4][136]
        int k = tid >> 1, half = tid & 1;
        float2 v = ((const float2*)c_wout)[tid];
        SCWT[(half * 2 + 0) * 136 + k] = v.x;
        SCWT[(half * 2 + 1) * 136 + k] = v.y;
    }
    __syncthreads();

    // ---- gather h[row]|h[col] into A cols 0..255 (fp16) ----
#pragma unroll 4
    for (int idx = tid; idx < ME * 64; idx += ETHREADS) {
        int e = idx >> 6, p4 = idx & 63;
        int half = p4 >> 5, q = p4 & 31;
        int node = half ? SCOL[e] : SROW[e];
        float4 v = ((const float4*)(h + node * HID))[q];
        store4A(sm, e, half * 128 + q * 4, v);
    }
    // ---- rad features cols 256..287; coord_diff to SCD ----
    if (tid < ME) {
        int e = tid;
        const float4* c4i = (const float4*)(coord + SROW[e] * 12);
        const float4* c4j = (const float4*)(coord + SCOL[e] * 12);
        float4 i0 = c4i[0], i1 = c4i[1], i2 = c4i[2];
        float4 j0 = c4j[0], j1 = c4j[1], j2 = c4j[2];
        float a[12] = {i0.x,i0.y,i0.z,i0.w,i1.x,i1.y,i1.z,i1.w,i2.x,i2.y,i2.z,i2.w};
        float b[12] = {j0.x,j0.y,j0.z,j0.w,j1.x,j1.y,j1.z,j1.w,j2.x,j2.y,j2.z,j2.w};
        float d[12];
#pragma unroll
        for (int i = 0; i < 12; i++) { d[i] = a[i] - b[i]; SCD[e * 12 + i] = d[i]; }
        float radv[32];
#pragma unroll
        for (int c = 0; c < 4; c++) {
#pragma unroll
            for (int f = 0; f < 4; f++) {
                float r = d[c*3+0]*d[f*3+0] + d[c*3+1]*d[f*3+1] + d[c*3+2]*d[f*3+2];
                float dx = a[c*3+0]-b[f*3+0], dy = a[c*3+1]-b[f*3+1], dz = a[c*3+2]-b[f*3+2];
                float d2 = dx*dx + dy*dy + dz*dz;
                radv[c*8 + f]     = r * SINV[c*8 + f];
                radv[c*8 + 4 + f] = sqrtf(d2) * SINV[c*8 + 4 + f];
            }
        }
#pragma unroll
        for (int q = 0; q < 32; q += 4)
            store4A(sm, e, 256 + q, make_float4(radv[q], radv[q+1], radv[q+2], radv[q+3]));
    }

    const int wm = wid & 3, wn = wid >> 2;
    const int r0 = wm * 32, n0 = wn * 32;
    float acc[2][4][4];

    // ========== GEMM1: t1 = silu(eh @ W1 + b1) -> A cols 0..127 (K=288) ===
    if (tid < 128) SBIAS[tid] = e_b1[tid];
    run_gemm_e<288>(sm, smem_base, acc, 0, g_w1t, tid, lane, r0, n0);
    epi_store_e(sm, acc, SBIAS, 0, lane, r0, n0);
    __syncthreads();

    // ========== GEMM2: m = silu(t1 @ W2 + b2) -> A cols 128..255 ==========
    if (tid < 128) SBIAS[tid] = e_b2[tid];
    run_gemm_e<128>(sm, smem_base, acc, 0, g_w2t, tid, lane, r0, n0);
    epi_store_e(sm, acc, SBIAS, 128, lane, r0, n0);
    __syncthreads();

    // ---- nagg scatter: coalesced red.v4 from fp16 m in smem ----
#pragma unroll 4
    for (int idx = tid; idx < ME * 32; idx += ETHREADS) {
        int e = idx >> 5, q = (idx & 31) * 4;
        uint2 hv = *(const uint2*)(sm + e * LDA_B + (128 + q) * 2);
        __half2 p0 = *reinterpret_cast<__half2*>(&hv.x);
        __half2 p1 = *reinterpret_cast<__half2*>(&hv.y);
        float2 f0 = __half22float2(p0), f1 = __half22float2(p1);
        float* dst = g_nagg + (size_t)SROW[e] * HID + q;
        asm volatile("red.global.add.v4.f32 [%0], {%1,%2,%3,%4};"
                     :: "l"(dst), "f"(f0.x), "f"(f0.y), "f"(f1.x), "f"(f1.y)
                     : "memory");
    }

    // ========== GEMM3: t2 = silu(m @ c_w1 + b) -> fp32 buffer =============
    if (tid < 128) SBIAS[tid] = c_b1[tid];
    run_gemm_e<128>(sm, smem_base, acc, 128, g_w3t, tid, lane, r0, n0);
    {
        float* t2f = (float*)sm;            // [128 x 132] fp32; A done after GEMM3
#pragma unroll
        for (int mt = 0; mt < 2; mt++) {
            int ra = r0 + mt * 16 + (lane >> 2);
            int rb = ra + 8;
#pragma unroll
            for (int nb = 0; nb < 4; nb++) {
                int c = n0 + nb * 8 + (lane & 3) * 2;
                float b0 = SBIAS[c], b1 = SBIAS[c + 1];
                *(float2*)(t2f + ra * 132 + c) =
                    make_float2(silu_f(acc[mt][nb][0] + b0), silu_f(acc[mt][nb][1] + b1));
                *(float2*)(t2f + rb * 132 + c) =
                    make_float2(silu_f(acc[mt][nb][2] + b0), silu_f(acc[mt][nb][3] + b1));
            }
        }
    }
    __syncthreads();

    // ========== w = t2 @ c_wout (float4 dot); coord atomics ===============
    if (tid < ME * 4) {
        int e = tid >> 2, c = tid & 3;
        const float4* tr4 = (const float4*)((const float*)sm + e * 132);
        const float4* cw4 = (const float4*)(SCWT + c * 136);
        float w = 0.0f;
#pragma unroll
        for (int i = 0; i < 32; i++) {
            float4 t = tr4[i], uq = cw4[i];
            w += t.x * uq.x + t.y * uq.y + t.z * uq.z + t.w * uq.w;
        }
        int node = SROW[e];
        const float* cd = SCD + e * 12 + c * 3;
        atomicAdd(&g_agg[node * 12 + c * 3 + 0], cd[0] * w);
        atomicAdd(&g_agg[node * 12 + c * 3 + 1], cd[1] * w);
        atomicAdd(&g_agg[node * 12 + c * 3 + 2], cd[2] * w);
        if (c == 0) atomicAdd(&g_cnt[node], 1.0f);
    }
}

// ============================================================================
// NODE GEMM machinery (64 rows/CTA, 256 threads, 2x4 warp grid, tile 32x32)
// ============================================================================
#define NSTG 5

__device__ __forceinline__ void ld_stageN(uint4 (&stg)[NSTG],
                                          const unsigned char* __restrict__ wsrc,
                                          int byteoff, int n4, int tid)
{
    const uint4* s = (const uint4*)(wsrc + byteoff);
#pragma unroll
    for (int i = 0; i < NSTG; i++) {
        int idx = tid + i * NTHREADS;
        if (idx < n4) stg[i] = s[idx];
    }
}

template <int KTOT>
__device__ __forceinline__ void run_gemm_n(
    unsigned char* sm, uint32_t smem_base, float (&acc)[2][4][4],
    int a_col_base, const unsigned char* __restrict__ wsrc,
    int tid, int lane, int r0, int n0)
{
#pragma unroll
    for (int mt = 0; mt < 2; mt++)
#pragma unroll
        for (int nb = 0; nb < 4; nb++)
#pragma unroll
            for (int i = 0; i < 4; i++) acc[mt][nb][i] = 0.0f;

    uint4 stg[NSTG];
    constexpr int R0 = (KTOT < 64) ? KTOT : 64;
    ld_stageN(stg, wsrc, 0, R0 * 17, tid);

#pragma unroll
    for (int k0 = 0; k0 < KTOT; k0 += 64) {
        const int rows = (KTOT - k0 < 64) ? (KTOT - k0) : 64;
        const int cn4 = rows * 17;
        __syncthreads();
        {
            uint4* db = (uint4*)(sm + NB_OFF);
#pragma unroll
            for (int i = 0; i < NSTG; i++) {
                int idx = tid + i * NTHREADS;
                if (idx < cn4) db[idx] = stg[i];
            }
        }
        __syncthreads();
        if (k0 + 64 < KTOT) {
            const int nrows = (KTOT - k0 - 64 < 64) ? (KTOT - k0 - 64) : 64;
            ld_stageN(stg, wsrc, (k0 + 64) * LDB_B, nrows * 17, tid);
        }
        const int nks = rows >> 4;
#pragma unroll
        for (int ks = 0; ks < 4; ks++) {
            if (ks >= nks) break;
            int kcol = a_col_base + k0 + ks * 16;
            uint32_t ah[2][4];
            uint32_t a_off = (uint32_t)((r0 + (lane & 15)) * LDA_B + (kcol + (lane >> 4) * 8) * 2);
            ldm_x4(ah[0], smem_base + NA_OFF + a_off);
            ldm_x4(ah[1], smem_base + NA_OFF + a_off + 16 * LDA_B);
            uint32_t bh[2][4];
            uint32_t b_off = (uint32_t)((ks * 16 + (lane & 15)) * LDB_B + (n0 + (lane >> 4) * 8) * 2);
#pragma unroll
            for (int nt = 0; nt < 2; nt++)
                ldm_x4_t(bh[nt], smem_base + NB_OFF + b_off + nt * 32);
#pragma unroll
            for (int mt = 0; mt < 2; mt++)
#pragma unroll
                for (int nt = 0; nt < 2; nt++) {
                    mma_f16(acc[mt][2*nt],   ah[mt], bh[nt][0], bh[nt][1]);
                    mma_f16(acc[mt][2*nt+1], ah[mt], bh[nt][2], bh[nt][3]);
                }
        }
    }
    __syncthreads();
}

__global__ void __launch_bounds__(NTHREADS, 3)
node_kernel(const float* __restrict__ h, const float* __restrict__ coord,
            const float* __restrict__ n_b1, const float* __restrict__ n_b2,
            float* __restrict__ out_h, float* __restrict__ out_coord)
{
    extern __shared__ unsigned char sm[];
    const int tid  = threadIdx.x;
    const int wid  = tid >> 5;
    const int lane = tid & 31;
    const int nb0  = blockIdx.x * MN;
    uint32_t smem_base = smem_to_u32(sm);
    float* SBIAS = (float*)(sm + NOF_BIAS);

    // ---- gather h[n] | nagg[n] into A cols 0..255 (fp16) ----
#pragma unroll 4
    for (int idx = tid; idx < MN * 64; idx += NTHREADS) {
        int r = idx >> 6, p4 = idx & 63;
        int half = p4 >> 5, q = p4 & 31;
        int n = nb0 + r;
        float4 v = make_float4(0.f, 0.f, 0.f, 0.f);
        if (n < N_NODE)
            v = half ? ((const float4*)(g_nagg + n * HID))[q]
                     : ((const float4*)(h + n * HID))[q];
        store4A(sm, r, half * 128 + q * 4, v);
    }

    const int wm = wid & 1, wn = wid >> 1;
    const int r0 = wm * 32, n0 = wn * 32;
    float acc[2][4][4];

    // ========== GEMM1: t = silu(nin @ nW1 + b1) -> A cols 0..127 ==========
    if (tid < 128) SBIAS[tid] = n_b1[tid];
    run_gemm_n<256>(sm, smem_base, acc, 0, g_nw1t, tid, lane, r0, n0);
    {
#pragma unroll
        for (int mt = 0; mt < 2; mt++) {
            int ra = r0 + mt * 16 + (lane >> 2);
            int rb = ra + 8;
#pragma unroll
            for (int nb = 0; nb < 4; nb++) {
                int c = n0 + nb * 8 + (lane & 3) * 2;
                float b0 = SBIAS[c], b1 = SBIAS[c + 1];
                *(uint32_t*)(sm + ra * LDA_B + c * 2) =
                    pack2h(silu_f(acc[mt][nb][0] + b0), silu_f(acc[mt][nb][1] + b1));
                *(uint32_t*)(sm + rb * LDA_B + c * 2) =
                    pack2h(silu_f(acc[mt][nb][2] + b0), silu_f(acc[mt][nb][3] + b1));
            }
        }
    }
    __syncthreads();

    // ========== GEMM2: hn = t @ nW2 + b2 ; out_h = h + hn =================
    if (tid < 128) SBIAS[tid] = n_b2[tid];
    run_gemm_n<128>(sm, smem_base, acc, 0, g_nw2t, tid, lane, r0, n0);
    {
#pragma unroll
        for (int mt = 0; mt < 2; mt++) {
            int ra = r0 + mt * 16 + (lane >> 2);
            int rb = ra + 8;
            int na = nb0 + ra, nbv = nb0 + rb;
#pragma unroll
            for (int nb = 0; nb < 4; nb++) {
                int c = n0 + nb * 8 + (lane & 3) * 2;
                float b0 = SBIAS[c], b1 = SBIAS[c + 1];
                if (na < N_NODE) {
                    float2 hv = *(const float2*)(h + na * HID + c);
                    *(float2*)(out_h + na * HID + c) =
                        make_float2(acc[mt][nb][0] + b0 + hv.x,
                                    acc[mt][nb][1] + b1 + hv.y);
                }
                if (nbv < N_NODE) {
                    float2 hv = *(const float2*)(h + nbv * HID + c);
                    *(float2*)(out_h + nbv * HID + c) =
                        make_float2(acc[mt][nb][2] + b0 + hv.x,
                                    acc[mt][nb][3] + b1 + hv.y);
                }
            }
        }
    }
    // ---- coord epilogue ----
    for (int idx = tid; idx < MN * 12; idx += NTHREADS) {
        int r = idx / 12, d = idx % 12;
        int n = nb0 + r;
        if (n < N_NODE) {
            float cnt = fmaxf(g_cnt[n], 1.0f);
            out_coord[n * 12 + d] = coord[n * 12 + d] + g_agg[n * 12 + d] / cnt;
        }
    }
}

// ============================================================================
extern "C" void kernel_launch(void* const* d_in, const int* in_sizes, int n_in,
                              void* d_out, int out_size)
{
    const float* h      = (const float*)d_in[0];
    const float* coord  = (const float*)d_in[1];
    const int*   row    = (const int*)d_in[2];
    const int*   col    = (const int*)d_in[3];
    const float* e_w1   = (const float*)d_in[4];
    const float* e_b1   = (const float*)d_in[5];
    const float* e_w2   = (const float*)d_in[6];
    const float* e_b2   = (const float*)d_in[7];
    const float* c_w1   = (const float*)d_in[8];
    const float* c_b1   = (const float*)d_in[9];
    const float* c_wout = (const float*)d_in[10];
    const float* n_w1   = (const float*)d_in[11];
    const float* n_b1   = (const float*)d_in[12];
    const float* n_w2   = (const float*)d_in[13];
    const float* n_b2   = (const float*)d_in[14];

    float* out_h     = (float*)d_out;
    float* out_coord = out_h + N_NODE * HID;

    void *p_sumsq, *p_nagg, *p_agg, *p_cnt;
    cudaGetSymbolAddress(&p_sumsq, g_sumsq);
    cudaGetSymbolAddress(&p_nagg,  g_nagg);
    cudaGetSymbolAddress(&p_agg,   g_agg);
    cudaGetSymbolAddress(&p_cnt,   g_cnt);
    cudaMemsetAsync(p_sumsq, 0, 32 * sizeof(float));
    cudaMemsetAsync(p_nagg,  0, N_NODE * HID * sizeof(float));
    cudaMemsetAsync(p_agg,   0, N_NODE * 12 * sizeof(float));
    cudaMemsetAsync(p_cnt,   0, N_NODE * sizeof(float));

    cudaFuncSetAttribute(edge_kernel, cudaFuncAttributeMaxDynamicSharedMemorySize,
                         SMEM_EDGE_BYTES);
    cudaFuncSetAttribute(node_kernel, cudaFuncAttributeMaxDynamicSharedMemorySize,
                         SMEM_NODE_BYTES);

    prep_sumsq_kernel<<<PREP_BLOCKS + SUMSQ_BLOCKS, 256>>>(
        e_w1, e_w2, c_w1, n_w1, n_w2, coord, row, col);
    edge_kernel<<<N_EDGE / ME, ETHREADS, SMEM_EDGE_BYTES>>>(
        h, coord, row, col, e_b1, e_b2, c_b1, c_wout);
    node_kernel<<<(N_NODE + MN - 1) / MN, NTHREADS, SMEM_NODE_BYTES>>>(
        h, coord, n_b1, n_b2, out_h, out_coord);
}

// round 17
// speedup vs baseline: 1.7587x; 1.0169x over previous
#include <cuda_runtime.h>
#include <cuda_fp16.h>
#include <math.h>
#include <stdint.h>

#define N_NODE 10000
#define N_EDGE 320000
#define HID    128
#define NC     4

// ---------------- edge kernel geometry (ME=128, 512 thr, occ 2) ------------
#define ME      128           // edges per CTA
#define ETHREADS 512
#define LDA_B   656           // A row stride bytes
#define LDB_B   272           // B row stride bytes (136 fp16)
#define CHB     8704          // B chunk: 32 k-rows * 272 B
#define A_OFF   0             // fp16 A image: 128*656 = 83968 B
#define B_OFF   83968         // two ping-pong chunks: 2*8704 = 17408
#define OF_ROW  101376
#define OF_COL  101888
#define OF_INV  102400
#define OF_BIAS 102528
#define OF_CW   103040        // transposed c_wout: 4 x 136 fp32 = 2176 B
#define OF_CD   105216        // coord_diff: 128*12*4 = 6144 B
#define SMEM_EDGE_BYTES 111360

// ---------------- node kernel geometry (64 rows/CTA, 256 thr, occ 3) -------
#define NTHREADS 256
#define MN      64
#define NA_OFF  0             // 64*656 = 41984
#define NB_OFF  41984
#define NOF_BIAS 59392
#define SMEM_NODE_BYTES 60544

// ---------------- scratch ----------------
__device__ float g_sumsq[32];
__device__ float g_nagg[N_NODE * HID];
__device__ float g_agg[N_NODE * NC * 3];
__device__ float g_cnt[N_NODE];
// weight images: [K x 128] fp16, row stride 272 B
__device__ __align__(16) unsigned char g_w1t[288 * LDB_B];
__device__ __align__(16) unsigned char g_w2t[128 * LDB_B];
__device__ __align__(16) unsigned char g_w3t[128 * LDB_B];
__device__ __align__(16) unsigned char g_nw1t[256 * LDB_B];
__device__ __align__(16) unsigned char g_nw2t[128 * LDB_B];

__device__ __forceinline__ float silu_f(float x) {
    return __fdividef(x, 1.0f + __expf(-x));
}

__device__ __forceinline__ uint32_t smem_to_u32(const void* p) {
    uint32_t a;
    asm("{ .reg .u64 t; cvta.to.shared.u64 t, %1; cvt.u32.u64 %0, t; }" : "=r"(a) : "l"(p));
    return a;
}
__device__ __forceinline__ void ldm_x4(uint32_t (&r)[4], uint32_t addr) {
    asm volatile("ldmatrix.sync.aligned.m8n8.x4.shared.b16 {%0,%1,%2,%3}, [%4];"
                 : "=r"(r[0]), "=r"(r[1]), "=r"(r[2]), "=r"(r[3]) : "r"(addr));
}
__device__ __forceinline__ void ldm_x4_t(uint32_t (&r)[4], uint32_t addr) {
    asm volatile("ldmatrix.sync.aligned.m8n8.x4.trans.shared.b16 {%0,%1,%2,%3}, [%4];"
                 : "=r"(r[0]), "=r"(r[1]), "=r"(r[2]), "=r"(r[3]) : "r"(addr));
}
__device__ __forceinline__ void mma_f16(float (&d)[4], const uint32_t (&a)[4],
                                        uint32_t b0, uint32_t b1) {
    asm volatile("mma.sync.aligned.m16n8k16.row.col.f32.f16.f16.f32 "
                 "{%0,%1,%2,%3}, {%4,%5,%6,%7}, {%8,%9}, {%0,%1,%2,%3};"
                 : "+f"(d[0]), "+f"(d[1]), "+f"(d[2]), "+f"(d[3])
                 : "r"(a[0]), "r"(a[1]), "r"(a[2]), "r"(a[3]), "r"(b0), "r"(b1));
}
__device__ __forceinline__ void cp_async16(uint32_t dst, const void* src) {
    asm volatile("cp.async.cg.shared.global [%0], [%1], 16;" :: "r"(dst), "l"(src));
}
#define CP_COMMIT() asm volatile("cp.async.commit_group;" ::: "memory")
#define CP_WAIT0()  asm volatile("cp.async.wait_group 0;" ::: "memory")

__device__ __forceinline__ uint32_t pack2h(float a, float b) {
    __half2 t = __floats2half2_rn(a, b);
    return *reinterpret_cast<uint32_t*>(&t);
}
__device__ __forceinline__ void store4A(unsigned char* sm, int e, int col, float4 v) {
    uint32_t off = (uint32_t)(e * LDA_B + col * 2);
    *(uint2*)(sm + off) = make_uint2(pack2h(v.x, v.y), pack2h(v.z, v.w));
}

// ============================================================================
// Fused prep (4 elems/thread) + sumsq (8+1 edges/thread ILP).
// ============================================================================
#define PREP_BLOCKS  116
#define PREP_STRIDE  (PREP_BLOCKS * 256)     // 29696; 4*29696 = 118784 exact
#define SUMSQ_BLOCKS 148
#define SSTRIDE      (SUMSQ_BLOCKS * 256)    // 37888; 8*37888 = 303104

__device__ __forceinline__ void prep_decode(int idx, const float* w1, const float* w2,
                                            const float* w3, const float* nw1,
                                            const float* nw2,
                                            const float** W, unsigned char** dst, int* r)
{
    if (idx < 36864)       { *W = w1;  *dst = g_w1t;  *r = idx; }
    else if (idx < 53248)  { *W = w2;  *dst = g_w2t;  *r = idx - 36864; }
    else if (idx < 69632)  { *W = w3;  *dst = g_w3t;  *r = idx - 53248; }
    else if (idx < 102400) { *W = nw1; *dst = g_nw1t; *r = idx - 69632; }
    else                   { *W = nw2; *dst = g_nw2t; *r = idx - 102400; }
}

__device__ __forceinline__ void sumsq_accum(float (&p)[32],
                                            const float* __restrict__ coord,
                                            int ri, int ci)
{
    const float4* c4i = (const float4*)(coord + ri * 12);
    const float4* c4j = (const float4*)(coord + ci * 12);
    float4 i0 = c4i[0], i1 = c4i[1], i2 = c4i[2];
    float4 j0 = c4j[0], j1 = c4j[1], j2 = c4j[2];
    float a[12] = {i0.x,i0.y,i0.z,i0.w,i1.x,i1.y,i1.z,i1.w,i2.x,i2.y,i2.z,i2.w};
    float b[12] = {j0.x,j0.y,j0.z,j0.w,j1.x,j1.y,j1.z,j1.w,j2.x,j2.y,j2.z,j2.w};
    float d[12];
#pragma unroll
    for (int i = 0; i < 12; i++) d[i] = a[i] - b[i];
#pragma unroll
    for (int c = 0; c < 4; c++) {
#pragma unroll
        for (int f = 0; f < 4; f++) {
            float r = d[c*3+0]*d[f*3+0] + d[c*3+1]*d[f*3+1] + d[c*3+2]*d[f*3+2];
            float dx = a[c*3+0]-b[f*3+0], dy = a[c*3+1]-b[f*3+1], dz = a[c*3+2]-b[f*3+2];
            float d2 = dx*dx + dy*dy + dz*dz;
            p[c*8 + f]     += r * r;
            p[c*8 + 4 + f] += d2;
        }
    }
}

__global__ void prep_sumsq_kernel(const float* __restrict__ w1,
                                  const float* __restrict__ w2,
                                  const float* __restrict__ w3,
                                  const float* __restrict__ nw1,
                                  const float* __restrict__ nw2,
                                  const float* __restrict__ coord,
                                  const int* __restrict__ row,
                                  const int* __restrict__ col)
{
    int tid = threadIdx.x;
    if (blockIdx.x < PREP_BLOCKS) {
        int base = blockIdx.x * 256 + tid;
        const float* W[4]; unsigned char* dst[4]; int r[4];
#pragma unroll
        for (int j = 0; j < 4; j++)
            prep_decode(base + j * PREP_STRIDE, w1, w2, w3, nw1, nw2,
                        &W[j], &dst[j], &r[j]);
        float v[4];
#pragma unroll
        for (int j = 0; j < 4; j++)
            v[j] = W[j][(r[j] >> 7) * 128 + (r[j] & 127)];
#pragma unroll
        for (int j = 0; j < 4; j++)
            *(__half*)(dst[j] + (r[j] >> 7) * LDB_B + (r[j] & 127) * 2) =
                __float2half_rn(v[j]);
        return;
    }
    // ---- sumsq: 8 guaranteed edges + optional 9th per thread ----
    __shared__ float s_sum[32];
    if (tid < 32) s_sum[tid] = 0.0f;
    __syncthreads();
    float p[32];
#pragma unroll
    for (int i = 0; i < 32; i++) p[i] = 0.0f;
    int bid = blockIdx.x - PREP_BLOCKS;
    int e0 = bid * 256 + tid;                 // < 37888; e0+7*S < 303104 < N_EDGE
    int rr[9], cc[9];
#pragma unroll
    for (int k = 0; k < 8; k++) {
        rr[k] = row[e0 + k * SSTRIDE];
        cc[k] = col[e0 + k * SSTRIDE];
    }
    int e8 = e0 + 8 * SSTRIDE;
    bool h8 = (e8 < N_EDGE);
    rr[8] = 0; cc[8] = 0;
    if (h8) { rr[8] = row[e8]; cc[8] = col[e8]; }
#pragma unroll
    for (int k = 0; k < 8; k++)
        sumsq_accum(p, coord, rr[k], cc[k]);
    if (h8) sumsq_accum(p, coord, rr[8], cc[8]);
#pragma unroll
    for (int i = 0; i < 32; i++) atomicAdd(&s_sum[i], p[i]);
    __syncthreads();
    if (tid < 32) atomicAdd(&g_sumsq[tid], s_sum[tid]);
}

// ============================================================================
// cp.async staging of one 32-row B chunk (8704 B = 544 x 16B), 512 threads
// ============================================================================
__device__ __forceinline__ void cp_issue_chunk(uint32_t dst,
                                               const unsigned char* __restrict__ src,
                                               int tid)
{
#pragma unroll
    for (int i = 0; i < 2; i++) {
        int idx = tid + i * ETHREADS;
        if (idx < CHB / 16) cp_async16(dst + idx * 16, src + idx * 16);
    }
}

// ============================================================================
// EDGE GEMM: 16 warps in 4x4 grid, warp tile 32 rows x 32 cols, acc[2][4][4].
// cp.async double-buffered B (32-row chunks), one barrier per chunk.
// ============================================================================
template <int KTOT>
__device__ __forceinline__ void run_gemm_e(
    unsigned char* sm, uint32_t smem_base, float (&acc)[2][4][4],
    int a_col_base, const unsigned char* __restrict__ wsrc,
    int tid, int lane, int r0, int n0)
{
#pragma unroll
    for (int mt = 0; mt < 2; mt++)
#pragma unroll
        for (int nb = 0; nb < 4; nb++)
#pragma unroll
            for (int i = 0; i < 4; i++) acc[mt][nb][i] = 0.0f;

    constexpr int NCH = KTOT / 32;
    cp_issue_chunk(smem_base + B_OFF, wsrc, tid);
    CP_COMMIT();

#pragma unroll
    for (int c = 0; c < NCH; c++) {
        CP_WAIT0();
        __syncthreads();        // chunk c visible; all warps done with buf (c+1)&1
        if (c + 1 < NCH) {
            cp_issue_chunk(smem_base + B_OFF + ((c + 1) & 1) * CHB,
                           wsrc + (c + 1) * CHB, tid);
            CP_COMMIT();
        }
        uint32_t bbase = smem_base + B_OFF + (c & 1) * CHB;
#pragma unroll
        for (int ks = 0; ks < 2; ks++) {
            int kcol = a_col_base + c * 32 + ks * 16;
            uint32_t ah[2][4];
            uint32_t a_off = (uint32_t)((r0 + (lane & 15)) * LDA_B + (kcol + (lane >> 4) * 8) * 2);
            ldm_x4(ah[0], smem_base + A_OFF + a_off);
            ldm_x4(ah[1], smem_base + A_OFF + a_off + 16 * LDA_B);
            uint32_t bh[2][4];
            uint32_t b_off = (uint32_t)((ks * 16 + (lane & 15)) * LDB_B + (n0 + (lane >> 4) * 8) * 2);
#pragma unroll
            for (int nt = 0; nt < 2; nt++)
                ldm_x4_t(bh[nt], bbase + b_off + nt * 32);
#pragma unroll
            for (int mt = 0; mt < 2; mt++)
#pragma unroll
                for (int nt = 0; nt < 2; nt++) {
                    mma_f16(acc[mt][2*nt],   ah[mt], bh[nt][0], bh[nt][1]);
                    mma_f16(acc[mt][2*nt+1], ah[mt], bh[nt][2], bh[nt][3]);
                }
        }
    }
    __syncthreads();   // last chunk's MMAs complete in all warps before A reuse
}

// bias + silu + fp16-store to A cols [dstbase, dstbase+128)
__device__ __forceinline__ void epi_store_e(
    unsigned char* sm, float (&acc)[2][4][4], const float* __restrict__ SBIAS,
    int dstbase, int lane, int r0, int n0)
{
#pragma unroll
    for (int mt = 0; mt < 2; mt++) {
        int ra = r0 + mt * 16 + (lane >> 2);
        int rb = ra + 8;
#pragma unroll
        for (int nb = 0; nb < 4; nb++) {
            int c = n0 + nb * 8 + (lane & 3) * 2;
            float b0 = SBIAS[c], b1 = SBIAS[c + 1];
            float v0 = silu_f(acc[mt][nb][0] + b0);
            float v1 = silu_f(acc[mt][nb][1] + b1);
            float v2 = silu_f(acc[mt][nb][2] + b0);
            float v3 = silu_f(acc[mt][nb][3] + b1);
            *(uint32_t*)(sm + ra * LDA_B + (dstbase + c) * 2) = pack2h(v0, v1);
            *(uint32_t*)(sm + rb * LDA_B + (dstbase + c) * 2) = pack2h(v2, v3);
        }
    }
}

// ============================================================================
// Fused edge kernel: 128 edges / CTA, 512 threads, 16 warps (4x4), 2 CTAs/SM.
// ============================================================================
__global__ void __launch_bounds__(ETHREADS, 2)
edge_kernel(const float* __restrict__ h, const float* __restrict__ coord,
            const int* __restrict__ row, const int* __restrict__ col,
            const float* __restrict__ e_b1, const float* __restrict__ e_b2,
            const float* __restrict__ c_b1, const float* __restrict__ c_wout)
{
    extern __shared__ unsigned char sm[];
    const int tid  = threadIdx.x;
    const int wid  = tid >> 5;
    const int lane = tid & 31;
    const int e0   = blockIdx.x * ME;
    uint32_t smem_base = smem_to_u32(sm);

    int*   SROW  = (int*)(sm + OF_ROW);
    int*   SCOL  = (int*)(sm + OF_COL);
    float* SINV  = (float*)(sm + OF_INV);
    float* SBIAS = (float*)(sm + OF_BIAS);
    float* SCWT  = (float*)(sm + OF_CW);    // [4][136] transposed c_wout
    float* SCD   = (float*)(sm + OF_CD);

    if (tid < ME)  { SROW[tid] = row[e0 + tid]; SCOL[tid] = col[e0 + tid]; }
    if (tid < 32)  SINV[tid] = 1.0f / fmaxf(sqrtf(g_sumsq[tid]), 1e-12f);
    if (tid < 256) {   // transpose c_wout [128][4] -> SCWT [4][136]
        int k = tid >> 1, half = tid & 1;
        float2 v = ((const float2*)c_wout)[tid];
        SCWT[(half * 2 + 0) * 136 + k] = v.x;
        SCWT[(half * 2 + 1) * 136 + k] = v.y;
    }
    __syncthreads();

    // ---- gather h[row]|h[col] into A cols 0..255 (fp16) ----
#pragma unroll 4
    for (int idx = tid; idx < ME * 64; idx += ETHREADS) {
        int e = idx >> 6, p4 = idx & 63;
        int half = p4 >> 5, q = p4 & 31;
        int node = half ? SCOL[e] : SROW[e];
        float4 v = ((const float4*)(h + node * HID))[q];
        store4A(sm, e, half * 128 + q * 4, v);
    }
    // ---- rad features cols 256..287; coord_diff to SCD ----
    if (tid < ME) {
        int e = tid;
        const float4* c4i = (const float4*)(coord + SROW[e] * 12);
        const float4* c4j = (const float4*)(coord + SCOL[e] * 12);
        float4 i0 = c4i[0], i1 = c4i[1], i2 = c4i[2];
        float4 j0 = c4j[0], j1 = c4j[1], j2 = c4j[2];
        float a[12] = {i0.x,i0.y,i0.z,i0.w,i1.x,i1.y,i1.z,i1.w,i2.x,i2.y,i2.z,i2.w};
        float b[12] = {j0.x,j0.y,j0.z,j0.w,j1.x,j1.y,j1.z,j1.w,j2.x,j2.y,j2.z,j2.w};
        float d[12];
#pragma unroll
        for (int i = 0; i < 12; i++) { d[i] = a[i] - b[i]; SCD[e * 12 + i] = d[i]; }
        float radv[32];
#pragma unroll
        for (int c = 0; c < 4; c++) {
#pragma unroll
            for (int f = 0; f < 4; f++) {
                float r = d[c*3+0]*d[f*3+0] + d[c*3+1]*d[f*3+1] + d[c*3+2]*d[f*3+2];
                float dx = a[c*3+0]-b[f*3+0], dy = a[c*3+1]-b[f*3+1], dz = a[c*3+2]-b[f*3+2];
                float d2 = dx*dx + dy*dy + dz*dz;
                radv[c*8 + f]     = r * SINV[c*8 + f];
                radv[c*8 + 4 + f] = sqrtf(d2) * SINV[c*8 + 4 + f];
            }
        }
#pragma unroll
        for (int q = 0; q < 32; q += 4)
            store4A(sm, e, 256 + q, make_float4(radv[q], radv[q+1], radv[q+2], radv[q+3]));
    }

    const int wm = wid & 3, wn = wid >> 2;
    const int r0 = wm * 32, n0 = wn * 32;
    float acc[2][4][4];

    // ========== GEMM1: t1 = silu(eh @ W1 + b1) -> A cols 0..127 (K=288) ===
    if (tid < 128) SBIAS[tid] = e_b1[tid];
    run_gemm_e<288>(sm, smem_base, acc, 0, g_w1t, tid, lane, r0, n0);
    epi_store_e(sm, acc, SBIAS, 0, lane, r0, n0);
    __syncthreads();

    // ========== GEMM2: m = silu(t1 @ W2 + b2) -> A cols 128..255 ==========
    if (tid < 128) SBIAS[tid] = e_b2[tid];
    run_gemm_e<128>(sm, smem_base, acc, 0, g_w2t, tid, lane, r0, n0);
    epi_store_e(sm, acc, SBIAS, 128, lane, r0, n0);
    __syncthreads();

    // ---- nagg scatter: coalesced red.v4 from fp16 m in smem ----
#pragma unroll 4
    for (int idx = tid; idx < ME * 32; idx += ETHREADS) {
        int e = idx >> 5, q = (idx & 31) * 4;
        uint2 hv = *(const uint2*)(sm + e * LDA_B + (128 + q) * 2);
        __half2 p0 = *reinterpret_cast<__half2*>(&hv.x);
        __half2 p1 = *reinterpret_cast<__half2*>(&hv.y);
        float2 f0 = __half22float2(p0), f1 = __half22float2(p1);
        float* dst = g_nagg + (size_t)SROW[e] * HID + q;
        asm volatile("red.global.add.v4.f32 [%0], {%1,%2,%3,%4};"
                     :: "l"(dst), "f"(f0.x), "f"(f0.y), "f"(f1.x), "f"(f1.y)
                     : "memory");
    }

    // ========== GEMM3: t2 = silu(m @ c_w1 + b) -> fp32 buffer =============
    if (tid < 128) SBIAS[tid] = c_b1[tid];
    run_gemm_e<128>(sm, smem_base, acc, 128, g_w3t, tid, lane, r0, n0);
    {
        float* t2f = (float*)sm;            // [128 x 132] fp32; A done after GEMM3
#pragma unroll
        for (int mt = 0; mt < 2; mt++) {
            int ra = r0 + mt * 16 + (lane >> 2);
            int rb = ra + 8;
#pragma unroll
            for (int nb = 0; nb < 4; nb++) {
                int c = n0 + nb * 8 + (lane & 3) * 2;
                float b0 = SBIAS[c], b1 = SBIAS[c + 1];
                *(float2*)(t2f + ra * 132 + c) =
                    make_float2(silu_f(acc[mt][nb][0] + b0), silu_f(acc[mt][nb][1] + b1));
                *(float2*)(t2f + rb * 132 + c) =
                    make_float2(silu_f(acc[mt][nb][2] + b0), silu_f(acc[mt][nb][3] + b1));
            }
        }
    }
    __syncthreads();

    // ========== w = t2 @ c_wout (float4 dot); coord atomics ===============
    if (tid < ME * 4) {
        int e = tid >> 2, c = tid & 3;
        const float4* tr4 = (const float4*)((const float*)sm + e * 132);
        const float4* cw4 = (const float4*)(SCWT + c * 136);
        float w = 0.0f;
#pragma unroll
        for (int i = 0; i < 32; i++) {
            float4 t = tr4[i], uq = cw4[i];
            w += t.x * uq.x + t.y * uq.y + t.z * uq.z + t.w * uq.w;
        }
        int node = SROW[e];
        const float* cd = SCD + e * 12 + c * 3;
        atomicAdd(&g_agg[node * 12 + c * 3 + 0], cd[0] * w);
        atomicAdd(&g_agg[node * 12 + c * 3 + 1], cd[1] * w);
        atomicAdd(&g_agg[node * 12 + c * 3 + 2], cd[2] * w);
        if (c == 0) atomicAdd(&g_cnt[node], 1.0f);
    }
}

// ============================================================================
// NODE GEMM machinery (64 rows/CTA, 256 threads, 2x4 warp grid, tile 32x32)
// ============================================================================
#define NSTG 5

__device__ __forceinline__ void ld_stageN(uint4 (&stg)[NSTG],
                                          const unsigned char* __restrict__ wsrc,
                                          int byteoff, int n4, int tid)
{
    const uint4* s = (const uint4*)(wsrc + byteoff);
#pragma unroll
    for (int i = 0; i < NSTG; i++) {
        int idx = tid + i * NTHREADS;
        if (idx < n4) stg[i] = s[idx];
    }
}

template <int KTOT>
__device__ __forceinline__ void run_gemm_n(
    unsigned char* sm, uint32_t smem_base, float (&acc)[2][4][4],
    int a_col_base, const unsigned char* __restrict__ wsrc,
    int tid, int lane, int r0, int n0)
{
#pragma unroll
    for (int mt = 0; mt < 2; mt++)
#pragma unroll
        for (int nb = 0; nb < 4; nb++)
#pragma unroll
            for (int i = 0; i < 4; i++) acc[mt][nb][i] = 0.0f;

    uint4 stg[NSTG];
    constexpr int R0 = (KTOT < 64) ? KTOT : 64;
    ld_stageN(stg, wsrc, 0, R0 * 17, tid);

#pragma unroll
    for (int k0 = 0; k0 < KTOT; k0 += 64) {
        const int rows = (KTOT - k0 < 64) ? (KTOT - k0) : 64;
        const int cn4 = rows * 17;
        __syncthreads();
        {
            uint4* db = (uint4*)(sm + NB_OFF);
#pragma unroll
            for (int i = 0; i < NSTG; i++) {
                int idx = tid + i * NTHREADS;
                if (idx < cn4) db[idx] = stg[i];
            }
        }
        __syncthreads();
        if (k0 + 64 < KTOT) {
            const int nrows = (KTOT - k0 - 64 < 64) ? (KTOT - k0 - 64) : 64;
            ld_stageN(stg, wsrc, (k0 + 64) * LDB_B, nrows * 17, tid);
        }
        const int nks = rows >> 4;
#pragma unroll
        for (int ks = 0; ks < 4; ks++) {
            if (ks >= nks) break;
            int kcol = a_col_base + k0 + ks * 16;
            uint32_t ah[2][4];
            uint32_t a_off = (uint32_t)((r0 + (lane & 15)) * LDA_B + (kcol + (lane >> 4) * 8) * 2);
            ldm_x4(ah[0], smem_base + NA_OFF + a_off);
            ldm_x4(ah[1], smem_base + NA_OFF + a_off + 16 * LDA_B);
            uint32_t bh[2][4];
            uint32_t b_off = (uint32_t)((ks * 16 + (lane & 15)) * LDB_B + (n0 + (lane >> 4) * 8) * 2);
#pragma unroll
            for (int nt = 0; nt < 2; nt++)
                ldm_x4_t(bh[nt], smem_base + NB_OFF + b_off + nt * 32);
#pragma unroll
            for (int mt = 0; mt < 2; mt++)
#pragma unroll
                for (int nt = 0; nt < 2; nt++) {
                    mma_f16(acc[mt][2*nt],   ah[mt], bh[nt][0], bh[nt][1]);
                    mma_f16(acc[mt][2*nt+1], ah[mt], bh[nt][2], bh[nt][3]);
                }
        }
    }
    __syncthreads();
}

__global__ void __launch_bounds__(NTHREADS, 3)
node_kernel(const float* __restrict__ h, const float* __restrict__ coord,
            const float* __restrict__ n_b1, const float* __restrict__ n_b2,
            float* __restrict__ out_h, float* __restrict__ out_coord)
{
    extern __shared__ unsigned char sm[];
    const int tid  = threadIdx.x;
    const int wid  = tid >> 5;
    const int lane = tid & 31;
    const int nb0  = blockIdx.x * MN;
    uint32_t smem_base = smem_to_u32(sm);
    float* SBIAS = (float*)(sm + NOF_BIAS);

    // ---- gather h[n] | nagg[n] into A cols 0..255 (fp16) ----
#pragma unroll 4
    for (int idx = tid; idx < MN * 64; idx += NTHREADS) {
        int r = idx >> 6, p4 = idx & 63;
        int half = p4 >> 5, q = p4 & 31;
        int n = nb0 + r;
        float4 v = make_float4(0.f, 0.f, 0.f, 0.f);
        if (n < N_NODE)
            v = half ? ((const float4*)(g_nagg + n * HID))[q]
                     : ((const float4*)(h + n * HID))[q];
        store4A(sm, r, half * 128 + q * 4, v);
    }

    const int wm = wid & 1, wn = wid >> 1;
    const int r0 = wm * 32, n0 = wn * 32;
    float acc[2][4][4];

    // ========== GEMM1: t = silu(nin @ nW1 + b1) -> A cols 0..127 ==========
    if (tid < 128) SBIAS[tid] = n_b1[tid];
    run_gemm_n<256>(sm, smem_base, acc, 0, g_nw1t, tid, lane, r0, n0);
    {
#pragma unroll
        for (int mt = 0; mt < 2; mt++) {
            int ra = r0 + mt * 16 + (lane >> 2);
            int rb = ra + 8;
#pragma unroll
            for (int nb = 0; nb < 4; nb++) {
                int c = n0 + nb * 8 + (lane & 3) * 2;
                float b0 = SBIAS[c], b1 = SBIAS[c + 1];
                *(uint32_t*)(sm + ra * LDA_B + c * 2) =
                    pack2h(silu_f(acc[mt][nb][0] + b0), silu_f(acc[mt][nb][1] + b1));
                *(uint32_t*)(sm + rb * LDA_B + c * 2) =
                    pack2h(silu_f(acc[mt][nb][2] + b0), silu_f(acc[mt][nb][3] + b1));
            }
        }
    }
    __syncthreads();

    // ========== GEMM2: hn = t @ nW2 + b2 ; out_h = h + hn =================
    if (tid < 128) SBIAS[tid] = n_b2[tid];
    run_gemm_n<128>(sm, smem_base, acc, 0, g_nw2t, tid, lane, r0, n0);
    {
#pragma unroll
        for (int mt = 0; mt < 2; mt++) {
            int ra = r0 + mt * 16 + (lane >> 2);
            int rb = ra + 8;
            int na = nb0 + ra, nbv = nb0 + rb;
#pragma unroll
            for (int nb = 0; nb < 4; nb++) {
                int c = n0 + nb * 8 + (lane & 3) * 2;
                float b0 = SBIAS[c], b1 = SBIAS[c + 1];
                if (na < N_NODE) {
                    float2 hv = *(const float2*)(h + na * HID + c);
                    *(float2*)(out_h + na * HID + c) =
                        make_float2(acc[mt][nb][0] + b0 + hv.x,
                                    acc[mt][nb][1] + b1 + hv.y);
                }
                if (nbv < N_NODE) {
                    float2 hv = *(const float2*)(h + nbv * HID + c);
                    *(float2*)(out_h + nbv * HID + c) =
                        make_float2(acc[mt][nb][2] + b0 + hv.x,
                                    acc[mt][nb][3] + b1 + hv.y);
                }
            }
        }
    }
    // ---- coord epilogue ----
    for (int idx = tid; idx < MN * 12; idx += NTHREADS) {
        int r = idx / 12, d = idx % 12;
        int n = nb0 + r;
        if (n < N_NODE) {
            float cnt = fmaxf(g_cnt[n], 1.0f);
            out_coord[n * 12 + d] = coord[n * 12 + d] + g_agg[n * 12 + d] / cnt;
        }
    }
}

// ============================================================================
extern "C" void kernel_launch(void* const* d_in, const int* in_sizes, int n_in,
                              void* d_out, int out_size)
{
    const float* h      = (const float*)d_in[0];
    const float* coord  = (const float*)d_in[1];
    const int*   row    = (const int*)d_in[2];
    const int*   col    = (const int*)d_in[3];
    const float* e_w1   = (const float*)d_in[4];
    const float* e_b1   = (const float*)d_in[5];
    const float* e_w2   = (const float*)d_in[6];
    const float* e_b2   = (const float*)d_in[7];
    const float* c_w1   = (const float*)d_in[8];
    const float* c_b1   = (const float*)d_in[9];
    const float* c_wout = (const float*)d_in[10];
    const float* n_w1   = (const float*)d_in[11];
    const float* n_b1   = (const float*)d_in[12];
    const float* n_w2   = (const float*)d_in[13];
    const float* n_b2   = (const float*)d_in[14];

    float* out_h     = (float*)d_out;
    float* out_coord = out_h + N_NODE * HID;

    void *p_sumsq, *p_nagg, *p_agg, *p_cnt;
    cudaGetSymbolAddress(&p_sumsq, g_sumsq);
    cudaGetSymbolAddress(&p_nagg,  g_nagg);
    cudaGetSymbolAddress(&p_agg,   g_agg);
    cudaGetSymbolAddress(&p_cnt,   g_cnt);
    cudaMemsetAsync(p_sumsq, 0, 32 * sizeof(float));
    cudaMemsetAsync(p_nagg,  0, N_NODE * HID * sizeof(float));
    cudaMemsetAsync(p_agg,   0, N_NODE * 12 * sizeof(float));
    cudaMemsetAsync(p_cnt,   0, N_NODE * sizeof(float));

    cudaFuncSetAttribute(edge_kernel, cudaFuncAttributeMaxDynamicSharedMemorySize,
                         SMEM_EDGE_BYTES);
    cudaFuncSetAttribute(node_kernel, cudaFuncAttributeMaxDynamicSharedMemorySize,
                         SMEM_NODE_BYTES);

    prep_sumsq_kernel<<<PREP_BLOCKS + SUMSQ_BLOCKS, 256>>>(
        e_w1, e_w2, c_w1, n_w1, n_w2, coord, row, col);
    edge_kernel<<<N_EDGE / ME, ETHREADS, SMEM_EDGE_BYTES>>>(
        h, coord, row, col, e_b1, e_b2, c_b1, c_wout);
    node_kernel<<<(N_NODE + MN - 1) / MN, NTHREADS, SMEM_NODE_BYTES>>>(
        h, coord, n_b1, n_b2, out_h, out_coord);
}